// round 14
// baseline (speedup 1.0000x reference)
#include <cuda_runtime.h>
#include <cuda_fp16.h>
#include <math.h>

#define NN   50000
#define EE   800000
#define GG   16
#define SCH  1024
#define SNB  ((NN + SCH - 1) / SCH)   // 49

// ---------------- scratch (device globals; no allocation allowed) ----------------
__device__ int      g_count[NN];
__device__ int      g_cursor[NN];
__device__ int      g_rowstart[NN + 1];
__device__ int      g_bsum[SNB];
__device__ int2     g_csr[EE];           // packed {src, ea-bits}
__device__ __half2  g_wshi[128 * 128];   // SAGE W fp16, [k2][o]
__device__ __half2  g_w16_g1[32 * 128];
__device__ __half2  g_w16_g2[32 * 128];
__device__ __half2  g_w16_go[32 * 64];
__device__ __half   g_h16[(size_t)NN * 128];  // SAGE: [y|z] fp16; GAT: projected feats
__device__ __half   g_hA16[(size_t)NN * 64];
__device__ __half   g_hB16[(size_t)NN * 64];
__device__ float    g_ssrc[(size_t)NN * 2];
__device__ float    g_sdst[(size_t)NN * 2];
__device__ float    g_meane[NN];
__device__ float    g_cE[5];
__device__ float    g_pool[2 * GG * 64];
__device__ float    g_cnt[2 * GG];
__device__ unsigned g_done;

__device__ __forceinline__ void cp16(unsigned saddr, const void* g, unsigned sz) {
    asm volatile("cp.async.cg.shared.global [%0], [%1], 16, %2;"
                 :: "r"(saddr), "l"(g), "r"(sz));
}
__device__ __forceinline__ void cp_commit() { asm volatile("cp.async.commit_group;"); }
template <int N>
__device__ __forceinline__ void cp_wait() {
    asm volatile("cp.async.wait_group %0;" :: "n"(N));
}

// ---------------- prep (g_count/g_bsum zeroed by memset nodes on side stream) -----
__global__ void k_prep(const float* __restrict__ wl, const float* __restrict__ wr,
                       const float* __restrict__ w1, const float* __restrict__ w2,
                       const float* __restrict__ wo,
                       const float* __restrict__ we1, const float* __restrict__ ae1,
                       const float* __restrict__ we2, const float* __restrict__ ae2,
                       const float* __restrict__ weo, const float* __restrict__ aeo) {
    int i = blockIdx.x * blockDim.x + threadIdx.x;
    if (i == 0) g_done = 0;
    if (i < 2 * GG * 64) g_pool[i] = 0.f;
    if (i < 2 * GG) g_cnt[i] = 0.f;
    if (i < 128 * 128) {
        int k2 = i >> 7, o = i & 127;
        int k0 = 2 * k2, k1 = 2 * k2 + 1;
        float w0 = (o < 64) ? wl[o * 256 + k0] : wr[(o - 64) * 256 + k0];
        float w1v = (o < 64) ? wl[o * 256 + k1] : wr[(o - 64) * 256 + k1];
        g_wshi[i] = __floats2half2_rn(w0, w1v);
    }
    if (i < 32 * 128) {
        int k2 = i >> 7, o = i & 127;
        g_w16_g1[i] = __floats2half2_rn(w1[o * 64 + 2 * k2], w1[o * 64 + 2 * k2 + 1]);
        g_w16_g2[i] = __floats2half2_rn(w2[o * 64 + 2 * k2], w2[o * 64 + 2 * k2 + 1]);
    }
    if (i < 32 * 64) {
        int k2 = i >> 6, o = i & 63;
        g_w16_go[i] = __floats2half2_rn(wo[o * 64 + 2 * k2], wo[o * 64 + 2 * k2 + 1]);
    }
    if (blockIdx.x == 0 && threadIdx.x < 160) {
        int wid = threadIdx.x >> 5, lane = threadIdx.x & 31;
        const float *we, *ae;
        if      (wid == 0) { we = we1;      ae = ae1;      }
        else if (wid == 1) { we = we1 + 64; ae = ae1 + 64; }
        else if (wid == 2) { we = we2;      ae = ae2;      }
        else if (wid == 3) { we = we2 + 64; ae = ae2 + 64; }
        else               { we = weo;      ae = aeo;      }
        float p = we[lane] * ae[lane] + we[lane + 32] * ae[lane + 32];
#pragma unroll
        for (int o = 16; o; o >>= 1) p += __shfl_xor_sync(0xffffffffu, p, o);
        if (lane == 0) g_cE[wid] = p;
    }
}

// ---------------- CSR build ----------------
__global__ void k_hist(const int* __restrict__ dst) {
    int e4 = blockIdx.x * blockDim.x + threadIdx.x;
    if (e4 < EE / 4) {
        int4 d = *(const int4*)&dst[e4 * 4];
        atomicAdd(&g_count[d.x], 1);
        atomicAdd(&g_count[d.y], 1);
        atomicAdd(&g_count[d.z], 1);
        atomicAdd(&g_count[d.w], 1);
    }
}

// fused scan: 49 blocks; local scan + all-predecessor lookback (blocks co-resident)
__global__ void k_scanall() {
    __shared__ int wsum[8];
    __shared__ int pre;
    int b = blockIdx.x, tid = threadIdx.x, lane = tid & 31, wid = tid >> 5;
    int base = b * SCH + tid * 4;
    int c[4];
#pragma unroll
    for (int j = 0; j < 4; j++) c[j] = (base + j < NN) ? g_count[base + j] : 0;
    int tsum = c[0] + c[1] + c[2] + c[3];
    int s = tsum;
#pragma unroll
    for (int o = 1; o < 32; o <<= 1) {
        int t = __shfl_up_sync(0xffffffffu, s, o);
        if (lane >= o) s += t;
    }
    int wexcl = s - tsum;
    if (lane == 31) wsum[wid] = s;
    if (tid == 0) pre = 0;
    __syncthreads();
    if (tid == 0) {
        int run = 0;
#pragma unroll
        for (int w = 0; w < 8; w++) { int t = wsum[w]; wsum[w] = run; run += t; }
        *(volatile int*)&g_bsum[b] = run + 1;   // publish (0 = not ready)
        __threadfence();
    }
    __syncthreads();
    if (tid < b) {                               // b <= 48; blocks co-resident
        volatile int* p = g_bsum + tid;
        int v;
        do { v = *p; } while (v == 0);
        atomicAdd(&pre, v - 1);
    }
    __syncthreads();
    int off = pre + wsum[wid] + wexcl;
#pragma unroll
    for (int j = 0; j < 4; j++) {
        int i = base + j;
        if (i < NN) { g_rowstart[i] = off; g_cursor[i] = off; }
        off += c[j];
    }
    if (b == 0 && tid == 0) g_rowstart[NN] = EE;
}

__global__ void k_scatter(const int* __restrict__ src, const int* __restrict__ dst,
                          const float* __restrict__ ea) {
    int e = blockIdx.x * blockDim.x + threadIdx.x;
    if (e < EE) {
        int d = dst[e];
        int p = atomicAdd(&g_cursor[d], 1);
        g_csr[p] = make_int2(src[e], __float_as_int(ea[e]));
    }
}

// ---------------- SAGE GEMM: fp16 2-term (ah*bh + al*bh), BM=128, BK=32, 2-stage ---
#define ASTR 36
#define BSTR2 136
#define A_WORDS (128 * ASTR)
#define B_WORDS (16 * BSTR2)
#define STAGE_W (A_WORDS + B_WORDS)      // 6784 words = 27136 B

__device__ __forceinline__ void mma_f16(float* c, const unsigned* a, unsigned b0, unsigned b1) {
    asm volatile(
        "mma.sync.aligned.m16n8k16.row.col.f32.f16.f16.f32 "
        "{%0,%1,%2,%3}, {%4,%5,%6,%7}, {%8,%9}, {%0,%1,%2,%3};"
        : "+f"(c[0]), "+f"(c[1]), "+f"(c[2]), "+f"(c[3])
        : "r"(a[0]), "r"(a[1]), "r"(a[2]), "r"(a[3]), "r"(b0), "r"(b1));
}

__device__ __forceinline__ void split2(float2 p, unsigned& hi, unsigned& lo) {
    __half h0 = __float2half_rn(p.x), h1 = __float2half_rn(p.y);
    __half l0 = __float2half_rn(p.x - __half2float(h0));
    __half l1 = __float2half_rn(p.y - __half2float(h1));
    __half2 H = __halves2half2(h0, h1), L = __halves2half2(l0, l1);
    hi = *(unsigned*)&H; lo = *(unsigned*)&L;
}

__global__ __launch_bounds__(256) void k_gemm_f16x2(const float* __restrict__ x,
                                                    const __half2* __restrict__ whi,
                                                    __half* __restrict__ h16) {
    extern __shared__ unsigned sm[];
    const int tid = threadIdx.x;
    const int lane = tid & 31, wid = tid >> 5;
    const int wm = wid & 3, wn = wid >> 2;
    const int brow = blockIdx.x * 128;
    const int gid = lane >> 2, tig = lane & 3;

    unsigned smbase = (unsigned)__cvta_generic_to_shared((void*)sm);

    auto load_stage = [&](int kt, int st) {
        const int k0 = kt * 32;
        const int k2b = kt * 16;
        unsigned abase = smbase + (unsigned)(st * STAGE_W) * 4u;
        unsigned bbase = abase + (unsigned)A_WORDS * 4u;
#pragma unroll
        for (int i = 0; i < 4; i++) {
            int r = (tid >> 3) + i * 32;
            int gr = brow + r;
            unsigned sz = (gr < NN) ? 16u : 0u;
            cp16(abase + (unsigned)(r * ASTR + (tid & 7) * 4) * 4u,
                 &x[(size_t)gr * 256 + k0 + (tid & 7) * 4], sz);
        }
        {
            int kr = tid >> 5, c4 = (tid & 31) * 4;
            cp16(bbase + (unsigned)(kr * BSTR2 + c4) * 4u,
                 &whi[(size_t)(k2b + kr) * 128 + c4], 16u);
            cp16(bbase + (unsigned)((kr + 8) * BSTR2 + c4) * 4u,
                 &whi[(size_t)(k2b + kr + 8) * 128 + c4], 16u);
        }
        cp_commit();
    };

    float acc[2][8][4];
#pragma unroll
    for (int m = 0; m < 2; m++)
#pragma unroll
        for (int j = 0; j < 8; j++)
#pragma unroll
            for (int q = 0; q < 4; q++) acc[m][j][q] = 0.f;

    load_stage(0, 0);

    for (int kt = 0; kt < 8; kt++) {
        if (kt < 7) { load_stage(kt + 1, (kt + 1) & 1); cp_wait<1>(); }
        else cp_wait<0>();
        __syncthreads();

        const int st = kt & 1;
        const float* Araw = (const float*)(sm + st * STAGE_W);
        const unsigned* Bhi = sm + st * STAGE_W + A_WORDS;

#pragma unroll
        for (int ko2 = 0; ko2 < 16; ko2 += 8) {
            unsigned ah[2][4], al[2][4];
#pragma unroll
            for (int mt = 0; mt < 2; mt++) {
                int r = wm * 32 + mt * 16 + gid;
                const float* A0 = Araw + r * ASTR + ko2 * 2 + tig * 2;
                const float* A1 = Araw + (r + 8) * ASTR + ko2 * 2 + tig * 2;
                split2(*(const float2*)A0,       ah[mt][0], al[mt][0]);
                split2(*(const float2*)A1,       ah[mt][1], al[mt][1]);
                split2(*(const float2*)(A0 + 8), ah[mt][2], al[mt][2]);
                split2(*(const float2*)(A1 + 8), ah[mt][3], al[mt][3]);
            }
#pragma unroll
            for (int j = 0; j < 8; j++) {
                int col = wn * 64 + j * 8 + gid;
                unsigned b0h = Bhi[(ko2 + tig) * BSTR2 + col];
                unsigned b1h = Bhi[(ko2 + 4 + tig) * BSTR2 + col];
#pragma unroll
                for (int mt = 0; mt < 2; mt++) {
                    mma_f16(acc[mt][j], ah[mt], b0h, b1h);
                    mma_f16(acc[mt][j], al[mt], b0h, b1h);
                }
            }
        }
        __syncthreads();
    }

#pragma unroll
    for (int mt = 0; mt < 2; mt++) {
#pragma unroll
        for (int j = 0; j < 8; j++) {
            int col = wn * 64 + j * 8 + tig * 2;
            int r0 = brow + wm * 32 + mt * 16 + gid;
            int r1 = r0 + 8;
            __half2 h0 = __floats2half2_rn(acc[mt][j][0], acc[mt][j][1]);
            __half2 h1 = __floats2half2_rn(acc[mt][j][2], acc[mt][j][3]);
            if (r0 < NN) *(__half2*)&h16[(size_t)r0 * 128 + col] = h0;
            if (r1 < NN) *(__half2*)&h16[(size_t)r1 * 128 + col] = h1;
        }
    }
}

// ---------------- GAT-layer GEMM via fp16 HMMA (K=64 single tile) ----------------
template <int BN, int H>
__global__ __launch_bounds__(256) void k_hgemm(const __half* __restrict__ in,
                                               const __half2* __restrict__ Wt2,
                                               __half* __restrict__ out16,
                                               const float* __restrict__ as_,
                                               const float* __restrict__ ad_,
                                               float* __restrict__ ssrc,
                                               float* __restrict__ sdst) {
    constexpr int WN = BN / 2;
    constexpr int NJ = WN / 8;
    __shared__ __half  As[128][72];
    __shared__ __half2 Bs[32][BN + 4];
    __shared__ float   sred[2][2][128];

    const int tid = threadIdx.x;
    const int lane = tid & 31, wid = tid >> 5;
    const int wm = wid & 3, wn = wid >> 2;
    const int brow = blockIdx.x * 128;
    const int gid = lane >> 2, tig = lane & 3;

#pragma unroll
    for (int i = 0; i < 4; i++) {
        int q = tid + i * 256;
        int r = q >> 3, c8 = (q & 7) * 8;
        int gr = brow + r;
        uint4 v = make_uint4(0, 0, 0, 0);
        if (gr < NN) v = *(const uint4*)&in[(size_t)gr * 64 + c8];
        *(uint4*)&As[r][c8] = v;
    }
#pragma unroll
    for (int i = 0; i < (BN * 32) / 1024; i++) {
        int q = tid + i * 256;
        int kr = q / (BN / 4), c4 = (q % (BN / 4)) * 4;
        *(uint4*)&Bs[kr][c4] = *(const uint4*)&Wt2[kr * BN + c4];
    }
    __syncthreads();

    float acc[2][NJ][4];
#pragma unroll
    for (int mt = 0; mt < 2; mt++)
#pragma unroll
        for (int j = 0; j < NJ; j++)
#pragma unroll
            for (int q = 0; q < 4; q++) acc[mt][j][q] = 0.f;

#pragma unroll
    for (int ko = 0; ko < 4; ko++) {
        unsigned a[2][4];
#pragma unroll
        for (int mt = 0; mt < 2; mt++) {
            int r = wm * 32 + mt * 16 + gid;
            a[mt][0] = *(unsigned*)&As[r][ko * 16 + tig * 2];
            a[mt][1] = *(unsigned*)&As[r + 8][ko * 16 + tig * 2];
            a[mt][2] = *(unsigned*)&As[r][ko * 16 + 8 + tig * 2];
            a[mt][3] = *(unsigned*)&As[r + 8][ko * 16 + 8 + tig * 2];
        }
#pragma unroll
        for (int j = 0; j < NJ; j++) {
            int col = wn * WN + j * 8 + gid;
            unsigned b0 = *(unsigned*)&Bs[ko * 8 + tig][col];
            unsigned b1 = *(unsigned*)&Bs[ko * 8 + 4 + tig][col];
            mma_f16(acc[0][j], a[0], b0, b1);
            mma_f16(acc[1][j], a[1], b0, b1);
        }
    }

#pragma unroll
    for (int mt = 0; mt < 2; mt++) {
        int r0 = brow + wm * 32 + mt * 16 + gid;
        int r1 = r0 + 8;
        float ps0 = 0.f, pd0 = 0.f, ps1 = 0.f, pd1 = 0.f;
#pragma unroll
        for (int j = 0; j < NJ; j++) {
            int c = wn * WN + j * 8 + tig * 2;
            __half2 h0 = __floats2half2_rn(acc[mt][j][0], acc[mt][j][1]);
            __half2 h1 = __floats2half2_rn(acc[mt][j][2], acc[mt][j][3]);
            if (r0 < NN) *(__half2*)&out16[(size_t)r0 * BN + c] = h0;
            if (r1 < NN) *(__half2*)&out16[(size_t)r1 * BN + c] = h1;
            float a0 = as_[c], a1 = as_[c + 1];
            float d0 = ad_[c], d1 = ad_[c + 1];
            ps0 += acc[mt][j][0] * a0 + acc[mt][j][1] * a1;
            pd0 += acc[mt][j][0] * d0 + acc[mt][j][1] * d1;
            ps1 += acc[mt][j][2] * a0 + acc[mt][j][3] * a1;
            pd1 += acc[mt][j][2] * d0 + acc[mt][j][3] * d1;
        }
#pragma unroll
        for (int o = 2; o; o >>= 1) {
            ps0 += __shfl_down_sync(0xffffffffu, ps0, o, 4);
            pd0 += __shfl_down_sync(0xffffffffu, pd0, o, 4);
            ps1 += __shfl_down_sync(0xffffffffu, ps1, o, 4);
            pd1 += __shfl_down_sync(0xffffffffu, pd1, o, 4);
        }
        if (tig == 0) {
            if constexpr (H == 2) {
                if (r0 < NN) { ssrc[(size_t)r0 * 2 + wn] = ps0; sdst[(size_t)r0 * 2 + wn] = pd0; }
                if (r1 < NN) { ssrc[(size_t)r1 * 2 + wn] = ps1; sdst[(size_t)r1 * 2 + wn] = pd1; }
            } else {
                int rb = wm * 32 + mt * 16 + gid;
                sred[0][wn][rb] = ps0; sred[1][wn][rb] = pd0;
                sred[0][wn][rb + 8] = ps1; sred[1][wn][rb + 8] = pd1;
            }
        }
    }
    if constexpr (H == 1) {
        __syncthreads();
        if (tid < 128) {
            int gr = brow + tid;
            if (gr < NN) {
                ssrc[gr] = sred[0][0][tid] + sred[0][1][tid];
                sdst[gr] = sred[1][0][tid] + sred[1][1][tid];
            }
        }
    }
}

// ---------------- SAGE aggregate: warp per node ----------------
__global__ void k_sage(const float* __restrict__ bl) {
    int gw = (blockIdx.x * blockDim.x + threadIdx.x) >> 5;
    int lane = threadIdx.x & 31;
    if (gw >= NN) return;
    int rs = g_rowstart[gw], re = g_rowstart[gw + 1];
    const __half2* yh = (const __half2*)g_h16;
    float ax = 0.f, ay = 0.f, es = 0.f;
    for (int base = rs; base < re; base += 32) {
        int m = re - base; if (m > 32) m = 32;
        int sj = 0;
        if (lane < m) {
            int2 v = g_csr[base + lane];
            sj = v.x;
            es += __int_as_float(v.y);
        }
#pragma unroll 8
        for (int j = 0; j < m; j++) {
            int s = __shfl_sync(0xffffffffu, sj, j);
            float2 v = __half22float2(yh[(size_t)s * 64 + lane]);
            ax += v.x; ay += v.y;
        }
    }
#pragma unroll
    for (int o = 16; o; o >>= 1) es += __shfl_xor_sync(0xffffffffu, es, o);
    float inv = 1.f / fmaxf((float)(re - rs), 1.f);
    float2 z  = __half22float2(*(const __half2*)&g_h16[(size_t)gw * 128 + 64 + lane * 2]);
    float2 bb = *(const float2*)&bl[lane * 2];
    float rx = fmaxf(ax * inv + bb.x + z.x, 0.f);
    float ry = fmaxf(ay * inv + bb.y + z.y, 0.f);
    *(__half2*)&g_hA16[(size_t)gw * 64 + lane * 2] = __floats2half2_rn(rx, ry);
    if (lane == 0) g_meane[gw] = es * inv;
}

// ---------------- GAT H=2 edge pass, warp per node ---------------
__global__ void k_gat2(const float* __restrict__ ssrc,
                       const float* __restrict__ sdst, const float* __restrict__ bias,
                       __half* __restrict__ hout16, int ceoff) {
    int n = (blockIdx.x * blockDim.x + threadIdx.x) >> 5;
    int lane = threadIdx.x & 31;
    if (n >= NN) return;
    int rs = g_rowstart[n], re = g_rowstart[n + 1];
    const __half* hp16 = g_h16;

    int myhead = lane >> 4;
    float ce0 = g_cE[ceoff], ce1 = g_cE[ceoff + 1];
    float2 sdp = *(const float2*)&sdst[(size_t)n * 2];
    float den;
    float4 acc;
    {   // self-loop
        float2 ssp = *(const float2*)&ssrc[(size_t)n * 2];
        float me = g_meane[n];
        float a0 = ssp.x + sdp.x + me * ce0; a0 = a0 > 0.f ? a0 : 0.2f * a0;
        float a1 = ssp.y + sdp.y + me * ce1; a1 = a1 > 0.f ? a1 : 0.2f * a1;
        float w = __expf(myhead ? a1 : a0);
        uint2 raw = *(const uint2*)(hp16 + (size_t)n * 128 + lane * 4);
        float2 f0 = __half22float2(*(__half2*)&raw.x);
        float2 f1 = __half22float2(*(__half2*)&raw.y);
        den = w;
        acc.x = w * f0.x; acc.y = w * f0.y; acc.z = w * f1.x; acc.w = w * f1.y;
    }
    for (int base = rs; base < re; base += 32) {
        int m = re - base; if (m > 32) m = 32;
        int sj = 0; float w0j = 0.f, w1j = 0.f;
        if (lane < m) {
            int2 v = g_csr[base + lane];
            sj = v.x;
            float ea = __int_as_float(v.y);
            float2 ssp = *(const float2*)&ssrc[(size_t)sj * 2];
            float a0 = ssp.x + sdp.x + ea * ce0; a0 = a0 > 0.f ? a0 : 0.2f * a0;
            float a1 = ssp.y + sdp.y + ea * ce1; a1 = a1 > 0.f ? a1 : 0.2f * a1;
            w0j = __expf(a0); w1j = __expf(a1);
        }
#pragma unroll 8
        for (int j = 0; j < m; j++) {
            int s = __shfl_sync(0xffffffffu, sj, j);
            float w0 = __shfl_sync(0xffffffffu, w0j, j);
            float w1 = __shfl_sync(0xffffffffu, w1j, j);
            float w = myhead ? w1 : w0;
            uint2 raw = *(const uint2*)(hp16 + (size_t)s * 128 + lane * 4);
            float2 f0 = __half22float2(*(__half2*)&raw.x);
            float2 f1 = __half22float2(*(__half2*)&raw.y);
            den += w;
            acc.x = fmaf(w, f0.x, acc.x); acc.y = fmaf(w, f0.y, acc.y);
            acc.z = fmaf(w, f1.x, acc.z); acc.w = fmaf(w, f1.y, acc.w);
        }
    }
    float invd = 1.f / den;
    float4 v = make_float4(acc.x * invd, acc.y * invd, acc.z * invd, acc.w * invd);
    float4 o;
    o.x = __shfl_xor_sync(0xffffffffu, v.x, 16);
    o.y = __shfl_xor_sync(0xffffffffu, v.y, 16);
    o.z = __shfl_xor_sync(0xffffffffu, v.z, 16);
    o.w = __shfl_xor_sync(0xffffffffu, v.w, 16);
    if (lane < 16) {
        float4 bb = *(const float4*)&bias[lane * 4];
        __half2 p0 = __floats2half2_rn(fmaxf((v.x + o.x) * 0.5f + bb.x, 0.f),
                                       fmaxf((v.y + o.y) * 0.5f + bb.y, 0.f));
        __half2 p1 = __floats2half2_rn(fmaxf((v.z + o.z) * 0.5f + bb.z, 0.f),
                                       fmaxf((v.w + o.w) * 0.5f + bb.w, 0.f));
        uint2 u; u.x = *(unsigned*)&p0; u.y = *(unsigned*)&p1;
        *(uint2*)&hout16[(size_t)n * 64 + lane * 4] = u;
    }
}

// ---------------- GAT H=1 + pooling + fused last-block MLP ------------------------
__global__ void k_gat1(const float* __restrict__ ssrc, const float* __restrict__ sdst,
                       const float* __restrict__ bias,
                       const int* __restrict__ types, const int* __restrict__ batch,
                       const float* __restrict__ w1, const float* __restrict__ b1,
                       const float* __restrict__ w2, const float* __restrict__ b2,
                       float* __restrict__ out) {
    __shared__ float sr[2048];
    __shared__ float sh[1024];
    __shared__ int lastflag;
    int tid = threadIdx.x;
    int wid = tid >> 5, lane = tid & 31;
    int n = blockIdx.x * 8 + wid;
    bool valid = (n < NN);
    const __half* hp16 = g_h16;

    if (valid) {
        int rs = g_rowstart[n], re = g_rowstart[n + 1];
        float cem = g_cE[4];
        float sdm = sdst[n];
        float den;
        float2 acc;
        {
            float a = ssrc[n] + sdm + g_meane[n] * cem;
            a = a > 0.f ? a : 0.2f * a;
            float w = __expf(a);
            float2 f = __half22float2(*(const __half2*)(hp16 + (size_t)n * 64 + lane * 2));
            den = w; acc.x = w * f.x; acc.y = w * f.y;
        }
        for (int base = rs; base < re; base += 32) {
            int m = re - base; if (m > 32) m = 32;
            int sj = 0; float wj = 0.f;
            if (lane < m) {
                int2 v = g_csr[base + lane];
                sj = v.x;
                float ea = __int_as_float(v.y);
                float a = ssrc[sj] + sdm + ea * cem;
                a = a > 0.f ? a : 0.2f * a;
                wj = __expf(a);
            }
#pragma unroll 8
            for (int j = 0; j < m; j++) {
                int s = __shfl_sync(0xffffffffu, sj, j);
                float w = __shfl_sync(0xffffffffu, wj, j);
                float2 f = __half22float2(*(const __half2*)(hp16 + (size_t)s * 64 + lane * 2));
                den += w;
                acc.x = fmaf(w, f.x, acc.x); acc.y = fmaf(w, f.y, acc.y);
            }
        }
        float invd = 1.f / den;
        float2 bb = *(const float2*)&bias[lane * 2];
        float rx = fmaxf(acc.x * invd + bb.x, 0.f);
        float ry = fmaxf(acc.y * invd + bb.y, 0.f);
        int t = types[n];
        if (t == 1 || t == 2) {
            int g = batch[n];
            float* pb = &g_pool[((t - 1) * GG + g) * 64 + lane * 2];
            atomicAdd(pb, rx);
            atomicAdd(pb + 1, ry);
            if (lane == 0) atomicAdd(&g_cnt[(t - 1) * GG + g], 1.f);
        }
    }

    __syncthreads();
    if (tid == 0) {
        __threadfence();
        unsigned old = atomicInc(&g_done, gridDim.x - 1);
        lastflag = (old == gridDim.x - 1);
    }
    __syncthreads();
    if (!lastflag) return;

    for (int idx = tid; idx < 2048; idx += 256) {
        int g = idx >> 7, c = idx & 127;
        int p = c >> 6, cc = c & 63;
        float cnt = fmaxf(g_cnt[p * GG + g], 1.f);
        sr[idx] = g_pool[(p * GG + g) * 64 + cc] / cnt;
    }
    __syncthreads();
    for (int idx = tid; idx < 1024; idx += 256) {
        int g = idx >> 6, o = idx & 63;
        float a = b1[o];
#pragma unroll 8
        for (int c = 0; c < 128; c++) a = fmaf(sr[g * 128 + c], w1[o * 128 + c], a);
        sh[idx] = fmaxf(a, 0.f);
    }
    __syncthreads();
    if (tid < 16) {
        float a = b2[0];
#pragma unroll 8
        for (int o = 0; o < 64; o++) a = fmaf(sh[tid * 64 + o], w2[o], a);
        out[tid] = a;
    }
}

// ---------------- host ----------------
extern "C" void kernel_launch(void* const* d_in, const int* in_sizes, int n_in,
                              void* d_out, int out_size) {
    const float* x       = (const float*)d_in[0];
    const int*   ei      = (const int*)  d_in[1];
    const int*   types   = (const int*)  d_in[2];
    const float* eattr   = (const float*)d_in[3];
    const int*   batch   = (const int*)  d_in[4];
    const float* sage_wl = (const float*)d_in[5];
    const float* sage_bl = (const float*)d_in[6];
    const float* sage_wr = (const float*)d_in[7];
    const float* mlp_w1  = (const float*)d_in[8];
    const float* mlp_b1  = (const float*)d_in[9];
    const float* mlp_w2  = (const float*)d_in[10];
    const float* mlp_b2  = (const float*)d_in[11];
    const float* g1_w  = (const float*)d_in[12];
    const float* g1_as = (const float*)d_in[13];
    const float* g1_ad = (const float*)d_in[14];
    const float* g1_we = (const float*)d_in[15];
    const float* g1_ae = (const float*)d_in[16];
    const float* g1_b  = (const float*)d_in[17];
    const float* g2_w  = (const float*)d_in[18];
    const float* g2_as = (const float*)d_in[19];
    const float* g2_ad = (const float*)d_in[20];
    const float* g2_we = (const float*)d_in[21];
    const float* g2_ae = (const float*)d_in[22];
    const float* g2_b  = (const float*)d_in[23];
    const float* go_w  = (const float*)d_in[24];
    const float* go_as = (const float*)d_in[25];
    const float* go_ad = (const float*)d_in[26];
    const float* go_we = (const float*)d_in[27];
    const float* go_ae = (const float*)d_in[28];
    const float* go_b  = (const float*)d_in[29];

    const int* src = ei;
    const int* dst = ei + EE;

    float *p_ssrc, *p_sdst;
    int *p_count, *p_bsum;
    __half *p_h16, *p_hA16, *p_hB16;
    __half2 *p_wshi, *p_w1, *p_w2, *p_wo;
    cudaGetSymbolAddress((void**)&p_wshi, g_wshi);
    cudaGetSymbolAddress((void**)&p_w1, g_w16_g1);
    cudaGetSymbolAddress((void**)&p_w2, g_w16_g2);
    cudaGetSymbolAddress((void**)&p_wo, g_w16_go);
    cudaGetSymbolAddress((void**)&p_h16, g_h16);
    cudaGetSymbolAddress((void**)&p_hA16, g_hA16);
    cudaGetSymbolAddress((void**)&p_hB16, g_hB16);
    cudaGetSymbolAddress((void**)&p_ssrc, g_ssrc);
    cudaGetSymbolAddress((void**)&p_sdst, g_sdst);
    cudaGetSymbolAddress((void**)&p_count, g_count);
    cudaGetSymbolAddress((void**)&p_bsum, g_bsum);

    const int NWARP_GRID = (NN * 32 + 255) / 256;
    const int EGRID = (EE + 255) / 256;
    const int HG_GRID = (NN + 127) / 128;
    const int TF_GRID = (NN + 127) / 128;
    const int TF_SMEM = STAGE_W * 2 * 4;   // 54272 B (2 stages)

    cudaFuncSetAttribute(k_gemm_f16x2, cudaFuncAttributeMaxDynamicSharedMemorySize, TF_SMEM);

    static cudaStream_t s_side = nullptr;
    static cudaEvent_t s_ev0 = nullptr, s_ev2 = nullptr;
    if (!s_side) {
        cudaStreamCreateWithFlags(&s_side, cudaStreamNonBlocking);
        cudaEventCreateWithFlags(&s_ev0, cudaEventDisableTiming);
        cudaEventCreateWithFlags(&s_ev2, cudaEventDisableTiming);
    }

    // Fork FIRST (capture-legal), then CSR chain on side stream.
    cudaEventRecord(s_ev0, 0);
    cudaStreamWaitEvent(s_side, s_ev0, 0);
    cudaMemsetAsync(p_count, 0, NN * sizeof(int), s_side);
    cudaMemsetAsync(p_bsum, 0, SNB * sizeof(int), s_side);
    k_hist<<<(EE / 4 + 255) / 256, 256, 0, s_side>>>(dst);
    k_scanall<<<SNB, 256, 0, s_side>>>();

    // Main: prep + GEMM (GEMM stays in the profiled kernel slot)
    k_prep<<<(NN + 255) / 256, 256>>>(sage_wl, sage_wr, g1_w, g2_w, go_w,
                                      g1_we, g1_ae, g2_we, g2_ae, go_we, go_ae);
    k_gemm_f16x2<<<TF_GRID, 256, TF_SMEM>>>(x, p_wshi, p_h16);

    // Side: scatter, then join
    k_scatter<<<EGRID, 256, 0, s_side>>>(src, dst, eattr);
    cudaEventRecord(s_ev2, s_side);
    cudaStreamWaitEvent(0, s_ev2, 0);

    k_sage<<<NWARP_GRID, 256>>>(sage_bl);

    k_hgemm<128, 2><<<HG_GRID, 256>>>(p_hA16, p_w1, p_h16, g1_as, g1_ad, p_ssrc, p_sdst);
    k_gat2<<<NWARP_GRID, 256>>>(p_ssrc, p_sdst, g1_b, p_hB16, 0);

    k_hgemm<128, 2><<<HG_GRID, 256>>>(p_hB16, p_w2, p_h16, g2_as, g2_ad, p_ssrc, p_sdst);
    k_gat2<<<NWARP_GRID, 256>>>(p_ssrc, p_sdst, g2_b, p_hA16, 2);

    k_hgemm<64, 1><<<HG_GRID, 256>>>(p_hA16, p_wo, p_h16, go_as, go_ad, p_ssrc, p_sdst);
    k_gat1<<<NWARP_GRID, 256>>>(p_ssrc, p_sdst, go_b, types, batch,
                                mlp_w1, mlp_b1, mlp_w2, mlp_b2, (float*)d_out);
}

// round 15
// speedup vs baseline: 1.0468x; 1.0468x over previous
#include <cuda_runtime.h>
#include <cuda_fp16.h>
#include <math.h>

#define NN   50000
#define EE   800000
#define GG   16
#define SCH  1024
#define SNB  ((NN + SCH - 1) / SCH)   // 49

// ---------------- scratch (device globals; no allocation allowed) ----------------
__device__ int      g_count[NN];
__device__ int      g_cursor[NN];
__device__ int      g_rowstart[NN + 1];
__device__ int      g_bsum[SNB];
__device__ int      g_boff[SNB];
__device__ int2     g_csr[EE];           // packed {src, ea-bits}
__device__ __half2  g_wshi[128 * 128];   // SAGE W fp16, [k2][o]
__device__ __half2  g_w16_g1[32 * 128];
__device__ __half2  g_w16_g2[32 * 128];
__device__ __half2  g_w16_go[32 * 64];
__device__ __half   g_h16[(size_t)NN * 128];  // SAGE: [y|z] fp16; GAT: projected feats
__device__ __half   g_hA16[(size_t)NN * 64];
__device__ __half   g_hB16[(size_t)NN * 64];
__device__ float    g_ssrc[(size_t)NN * 2];
__device__ float    g_sdst[(size_t)NN * 2];
__device__ float    g_meane[NN];
__device__ float    g_cE[5];
__device__ float    g_pool[2 * GG * 64];
__device__ float    g_cnt[2 * GG];

__device__ __forceinline__ void cp16(unsigned saddr, const void* g, unsigned sz) {
    asm volatile("cp.async.cg.shared.global [%0], [%1], 16, %2;"
                 :: "r"(saddr), "l"(g), "r"(sz));
}
__device__ __forceinline__ void cp_commit() { asm volatile("cp.async.commit_group;"); }
template <int N>
__device__ __forceinline__ void cp_wait() {
    asm volatile("cp.async.wait_group %0;" :: "n"(N));
}

// ---------------- prep (g_count zeroed by memset node on side stream) -------------
__global__ void k_prep(const float* __restrict__ wl, const float* __restrict__ wr,
                       const float* __restrict__ w1, const float* __restrict__ w2,
                       const float* __restrict__ wo,
                       const float* __restrict__ we1, const float* __restrict__ ae1,
                       const float* __restrict__ we2, const float* __restrict__ ae2,
                       const float* __restrict__ weo, const float* __restrict__ aeo) {
    int i = blockIdx.x * blockDim.x + threadIdx.x;
    if (i < 2 * GG * 64) g_pool[i] = 0.f;
    if (i < 2 * GG) g_cnt[i] = 0.f;
    if (i < 128 * 128) {
        int k2 = i >> 7, o = i & 127;
        int k0 = 2 * k2, k1 = 2 * k2 + 1;
        float w0 = (o < 64) ? wl[o * 256 + k0] : wr[(o - 64) * 256 + k0];
        float w1v = (o < 64) ? wl[o * 256 + k1] : wr[(o - 64) * 256 + k1];
        g_wshi[i] = __floats2half2_rn(w0, w1v);
    }
    if (i < 32 * 128) {
        int k2 = i >> 7, o = i & 127;
        g_w16_g1[i] = __floats2half2_rn(w1[o * 64 + 2 * k2], w1[o * 64 + 2 * k2 + 1]);
        g_w16_g2[i] = __floats2half2_rn(w2[o * 64 + 2 * k2], w2[o * 64 + 2 * k2 + 1]);
    }
    if (i < 32 * 64) {
        int k2 = i >> 6, o = i & 63;
        g_w16_go[i] = __floats2half2_rn(wo[o * 64 + 2 * k2], wo[o * 64 + 2 * k2 + 1]);
    }
    if (blockIdx.x == 0 && threadIdx.x < 160) {
        int wid = threadIdx.x >> 5, lane = threadIdx.x & 31;
        const float *we, *ae;
        if      (wid == 0) { we = we1;      ae = ae1;      }
        else if (wid == 1) { we = we1 + 64; ae = ae1 + 64; }
        else if (wid == 2) { we = we2;      ae = ae2;      }
        else if (wid == 3) { we = we2 + 64; ae = ae2 + 64; }
        else               { we = weo;      ae = aeo;      }
        float p = we[lane] * ae[lane] + we[lane + 32] * ae[lane + 32];
#pragma unroll
        for (int o = 16; o; o >>= 1) p += __shfl_xor_sync(0xffffffffu, p, o);
        if (lane == 0) g_cE[wid] = p;
    }
}

// ---------------- CSR build ----------------
__global__ void k_hist(const int* __restrict__ dst) {
    int e4 = blockIdx.x * blockDim.x + threadIdx.x;
    if (e4 < EE / 4) {
        int4 d = *(const int4*)&dst[e4 * 4];
        atomicAdd(&g_count[d.x], 1);
        atomicAdd(&g_count[d.y], 1);
        atomicAdd(&g_count[d.z], 1);
        atomicAdd(&g_count[d.w], 1);
    }
}

__global__ void k_part() {
    __shared__ int ws[8];
    int b = blockIdx.x, tid = threadIdx.x;
    int base = b * SCH + tid * 4;
    int s = 0;
#pragma unroll
    for (int j = 0; j < 4; j++) { int i = base + j; if (i < NN) s += g_count[i]; }
#pragma unroll
    for (int o = 16; o; o >>= 1) s += __shfl_down_sync(0xffffffffu, s, o);
    if ((tid & 31) == 0) ws[tid >> 5] = s;
    __syncthreads();
    if (tid == 0) {
        int t = 0;
#pragma unroll
        for (int w = 0; w < 8; w++) t += ws[w];
        g_bsum[b] = t;
    }
}

__global__ void k_scan2() {
    __shared__ int w0s;
    int tid = threadIdx.x, lane = tid & 31, wid = tid >> 5;
    int v = (tid < SNB) ? g_bsum[tid] : 0;
    int s = v;
#pragma unroll
    for (int o = 1; o < 32; o <<= 1) {
        int t = __shfl_up_sync(0xffffffffu, s, o);
        if (lane >= o) s += t;
    }
    if (wid == 0 && lane == 31) w0s = s;
    __syncthreads();
    if (wid == 1) s += w0s;
    if (tid < SNB) g_boff[tid] = s - v;
}

__global__ void k_scanfinal() {
    __shared__ int wsum[8];
    int b = blockIdx.x, tid = threadIdx.x, lane = tid & 31, wid = tid >> 5;
    int base = b * SCH + tid * 4;
    int c[4];
#pragma unroll
    for (int j = 0; j < 4; j++) c[j] = (base + j < NN) ? g_count[base + j] : 0;
    int tsum = c[0] + c[1] + c[2] + c[3];
    int s = tsum;
#pragma unroll
    for (int o = 1; o < 32; o <<= 1) {
        int t = __shfl_up_sync(0xffffffffu, s, o);
        if (lane >= o) s += t;
    }
    int wexcl = s - tsum;
    if (lane == 31) wsum[wid] = s;
    __syncthreads();
    if (tid == 0) {
        int run = 0;
#pragma unroll
        for (int w = 0; w < 8; w++) { int t = wsum[w]; wsum[w] = run; run += t; }
    }
    __syncthreads();
    int off = g_boff[b] + wsum[wid] + wexcl;
#pragma unroll
    for (int j = 0; j < 4; j++) {
        int i = base + j;
        if (i < NN) { g_rowstart[i] = off; g_cursor[i] = off; }
        off += c[j];
    }
    if (b == 0 && tid == 0) g_rowstart[NN] = EE;
}

__global__ void k_scatter(const int* __restrict__ src, const int* __restrict__ dst,
                          const float* __restrict__ ea) {
    int e = blockIdx.x * blockDim.x + threadIdx.x;
    if (e < EE) {
        int d = dst[e];
        int p = atomicAdd(&g_cursor[d], 1);
        g_csr[p] = make_int2(src[e], __float_as_int(ea[e]));
    }
}

// ---------------- SAGE GEMM: fp16 2-term (ah*bh + al*bh), BM=128, BK=32, 2-stage ---
#define ASTR 36
#define BSTR2 136
#define A_WORDS (128 * ASTR)             // 4608 f32 words
#define B_WORDS (16 * BSTR2)             // 2176 half2 words
#define STAGE_W (A_WORDS + B_WORDS)      // 6784 words = 27136 B

__device__ __forceinline__ void mma_f16(float* c, const unsigned* a, unsigned b0, unsigned b1) {
    asm volatile(
        "mma.sync.aligned.m16n8k16.row.col.f32.f16.f16.f32 "
        "{%0,%1,%2,%3}, {%4,%5,%6,%7}, {%8,%9}, {%0,%1,%2,%3};"
        : "+f"(c[0]), "+f"(c[1]), "+f"(c[2]), "+f"(c[3])
        : "r"(a[0]), "r"(a[1]), "r"(a[2]), "r"(a[3]), "r"(b0), "r"(b1));
}

__device__ __forceinline__ void split2(float2 p, unsigned& hi, unsigned& lo) {
    __half h0 = __float2half_rn(p.x), h1 = __float2half_rn(p.y);
    __half l0 = __float2half_rn(p.x - __half2float(h0));
    __half l1 = __float2half_rn(p.y - __half2float(h1));
    __half2 H = __halves2half2(h0, h1), L = __halves2half2(l0, l1);
    hi = *(unsigned*)&H; lo = *(unsigned*)&L;
}

__global__ __launch_bounds__(256) void k_gemm_f16x2(const float* __restrict__ x,
                                                    const __half2* __restrict__ whi,
                                                    __half* __restrict__ h16) {
    extern __shared__ unsigned sm[];
    const int tid = threadIdx.x;
    const int lane = tid & 31, wid = tid >> 5;
    const int wm = wid & 3, wn = wid >> 2;
    const int brow = blockIdx.x * 128;
    const int gid = lane >> 2, tig = lane & 3;

    unsigned smbase = (unsigned)__cvta_generic_to_shared((void*)sm);

    auto load_stage = [&](int kt, int st) {
        const int k0 = kt * 32;
        const int k2b = kt * 16;
        unsigned abase = smbase + (unsigned)(st * STAGE_W) * 4u;
        unsigned bbase = abase + (unsigned)A_WORDS * 4u;
#pragma unroll
        for (int i = 0; i < 4; i++) {
            int r = (tid >> 3) + i * 32;
            int gr = brow + r;
            unsigned sz = (gr < NN) ? 16u : 0u;
            cp16(abase + (unsigned)(r * ASTR + (tid & 7) * 4) * 4u,
                 &x[(size_t)gr * 256 + k0 + (tid & 7) * 4], sz);
        }
        {
            int kr = tid >> 5, c4 = (tid & 31) * 4;
            cp16(bbase + (unsigned)(kr * BSTR2 + c4) * 4u,
                 &whi[(size_t)(k2b + kr) * 128 + c4], 16u);
            cp16(bbase + (unsigned)((kr + 8) * BSTR2 + c4) * 4u,
                 &whi[(size_t)(k2b + kr + 8) * 128 + c4], 16u);
        }
        cp_commit();
    };

    float acc[2][8][4];
#pragma unroll
    for (int m = 0; m < 2; m++)
#pragma unroll
        for (int j = 0; j < 8; j++)
#pragma unroll
            for (int q = 0; q < 4; q++) acc[m][j][q] = 0.f;

    load_stage(0, 0);

    for (int kt = 0; kt < 8; kt++) {
        if (kt < 7) { load_stage(kt + 1, (kt + 1) & 1); cp_wait<1>(); }
        else cp_wait<0>();
        __syncthreads();

        const int st = kt & 1;
        const float* Araw = (const float*)(sm + st * STAGE_W);
        const unsigned* Bhi = sm + st * STAGE_W + A_WORDS;

#pragma unroll
        for (int ko2 = 0; ko2 < 16; ko2 += 8) {
            unsigned ah[2][4], al[2][4];
#pragma unroll
            for (int mt = 0; mt < 2; mt++) {
                int r = wm * 32 + mt * 16 + gid;
                const float* A0 = Araw + r * ASTR + ko2 * 2 + tig * 2;
                const float* A1 = Araw + (r + 8) * ASTR + ko2 * 2 + tig * 2;
                split2(*(const float2*)A0,       ah[mt][0], al[mt][0]);
                split2(*(const float2*)A1,       ah[mt][1], al[mt][1]);
                split2(*(const float2*)(A0 + 8), ah[mt][2], al[mt][2]);
                split2(*(const float2*)(A1 + 8), ah[mt][3], al[mt][3]);
            }
#pragma unroll
            for (int j = 0; j < 8; j++) {
                int col = wn * 64 + j * 8 + gid;
                unsigned b0h = Bhi[(ko2 + tig) * BSTR2 + col];
                unsigned b1h = Bhi[(ko2 + 4 + tig) * BSTR2 + col];
#pragma unroll
                for (int mt = 0; mt < 2; mt++) {
                    mma_f16(acc[mt][j], ah[mt], b0h, b1h);
                    mma_f16(acc[mt][j], al[mt], b0h, b1h);
                }
            }
        }
        __syncthreads();
    }

#pragma unroll
    for (int mt = 0; mt < 2; mt++) {
#pragma unroll
        for (int j = 0; j < 8; j++) {
            int col = wn * 64 + j * 8 + tig * 2;
            int r0 = brow + wm * 32 + mt * 16 + gid;
            int r1 = r0 + 8;
            __half2 h0 = __floats2half2_rn(acc[mt][j][0], acc[mt][j][1]);
            __half2 h1 = __floats2half2_rn(acc[mt][j][2], acc[mt][j][3]);
            if (r0 < NN) *(__half2*)&h16[(size_t)r0 * 128 + col] = h0;
            if (r1 < NN) *(__half2*)&h16[(size_t)r1 * 128 + col] = h1;
        }
    }
}

// ---------------- GAT-layer GEMM via fp16 HMMA (K=64 single tile) ----------------
template <int BN, int H>
__global__ __launch_bounds__(256) void k_hgemm(const __half* __restrict__ in,
                                               const __half2* __restrict__ Wt2,
                                               __half* __restrict__ out16,
                                               const float* __restrict__ as_,
                                               const float* __restrict__ ad_,
                                               float* __restrict__ ssrc,
                                               float* __restrict__ sdst) {
    constexpr int WN = BN / 2;
    constexpr int NJ = WN / 8;
    __shared__ __half  As[128][72];
    __shared__ __half2 Bs[32][BN + 4];
    __shared__ float   sred[2][2][128];

    const int tid = threadIdx.x;
    const int lane = tid & 31, wid = tid >> 5;
    const int wm = wid & 3, wn = wid >> 2;
    const int brow = blockIdx.x * 128;
    const int gid = lane >> 2, tig = lane & 3;

#pragma unroll
    for (int i = 0; i < 4; i++) {
        int q = tid + i * 256;
        int r = q >> 3, c8 = (q & 7) * 8;
        int gr = brow + r;
        uint4 v = make_uint4(0, 0, 0, 0);
        if (gr < NN) v = *(const uint4*)&in[(size_t)gr * 64 + c8];
        *(uint4*)&As[r][c8] = v;
    }
#pragma unroll
    for (int i = 0; i < (BN * 32) / 1024; i++) {
        int q = tid + i * 256;
        int kr = q / (BN / 4), c4 = (q % (BN / 4)) * 4;
        *(uint4*)&Bs[kr][c4] = *(const uint4*)&Wt2[kr * BN + c4];
    }
    __syncthreads();

    float acc[2][NJ][4];
#pragma unroll
    for (int mt = 0; mt < 2; mt++)
#pragma unroll
        for (int j = 0; j < NJ; j++)
#pragma unroll
            for (int q = 0; q < 4; q++) acc[mt][j][q] = 0.f;

#pragma unroll
    for (int ko = 0; ko < 4; ko++) {
        unsigned a[2][4];
#pragma unroll
        for (int mt = 0; mt < 2; mt++) {
            int r = wm * 32 + mt * 16 + gid;
            a[mt][0] = *(unsigned*)&As[r][ko * 16 + tig * 2];
            a[mt][1] = *(unsigned*)&As[r + 8][ko * 16 + tig * 2];
            a[mt][2] = *(unsigned*)&As[r][ko * 16 + 8 + tig * 2];
            a[mt][3] = *(unsigned*)&As[r + 8][ko * 16 + 8 + tig * 2];
        }
#pragma unroll
        for (int j = 0; j < NJ; j++) {
            int col = wn * WN + j * 8 + gid;
            unsigned b0 = *(unsigned*)&Bs[ko * 8 + tig][col];
            unsigned b1 = *(unsigned*)&Bs[ko * 8 + 4 + tig][col];
            mma_f16(acc[0][j], a[0], b0, b1);
            mma_f16(acc[1][j], a[1], b0, b1);
        }
    }

#pragma unroll
    for (int mt = 0; mt < 2; mt++) {
        int r0 = brow + wm * 32 + mt * 16 + gid;
        int r1 = r0 + 8;
        float ps0 = 0.f, pd0 = 0.f, ps1 = 0.f, pd1 = 0.f;
#pragma unroll
        for (int j = 0; j < NJ; j++) {
            int c = wn * WN + j * 8 + tig * 2;
            __half2 h0 = __floats2half2_rn(acc[mt][j][0], acc[mt][j][1]);
            __half2 h1 = __floats2half2_rn(acc[mt][j][2], acc[mt][j][3]);
            if (r0 < NN) *(__half2*)&out16[(size_t)r0 * BN + c] = h0;
            if (r1 < NN) *(__half2*)&out16[(size_t)r1 * BN + c] = h1;
            float a0 = as_[c], a1 = as_[c + 1];
            float d0 = ad_[c], d1 = ad_[c + 1];
            ps0 += acc[mt][j][0] * a0 + acc[mt][j][1] * a1;
            pd0 += acc[mt][j][0] * d0 + acc[mt][j][1] * d1;
            ps1 += acc[mt][j][2] * a0 + acc[mt][j][3] * a1;
            pd1 += acc[mt][j][2] * d0 + acc[mt][j][3] * d1;
        }
#pragma unroll
        for (int o = 2; o; o >>= 1) {
            ps0 += __shfl_down_sync(0xffffffffu, ps0, o, 4);
            pd0 += __shfl_down_sync(0xffffffffu, pd0, o, 4);
            ps1 += __shfl_down_sync(0xffffffffu, ps1, o, 4);
            pd1 += __shfl_down_sync(0xffffffffu, pd1, o, 4);
        }
        if (tig == 0) {
            if constexpr (H == 2) {
                if (r0 < NN) { ssrc[(size_t)r0 * 2 + wn] = ps0; sdst[(size_t)r0 * 2 + wn] = pd0; }
                if (r1 < NN) { ssrc[(size_t)r1 * 2 + wn] = ps1; sdst[(size_t)r1 * 2 + wn] = pd1; }
            } else {
                int rb = wm * 32 + mt * 16 + gid;
                sred[0][wn][rb] = ps0; sred[1][wn][rb] = pd0;
                sred[0][wn][rb + 8] = ps1; sred[1][wn][rb + 8] = pd1;
            }
        }
    }
    if constexpr (H == 1) {
        __syncthreads();
        if (tid < 128) {
            int gr = brow + tid;
            if (gr < NN) {
                ssrc[gr] = sred[0][0][tid] + sred[0][1][tid];
                sdst[gr] = sred[1][0][tid] + sred[1][1][tid];
            }
        }
    }
}

// ---------------- SAGE aggregate: warp per node ----------------
__global__ void k_sage(const float* __restrict__ bl) {
    int gw = (blockIdx.x * blockDim.x + threadIdx.x) >> 5;
    int lane = threadIdx.x & 31;
    if (gw >= NN) return;
    int rs = g_rowstart[gw], re = g_rowstart[gw + 1];
    const __half2* yh = (const __half2*)g_h16;
    float ax = 0.f, ay = 0.f, es = 0.f;
    for (int base = rs; base < re; base += 32) {
        int m = re - base; if (m > 32) m = 32;
        int sj = 0;
        if (lane < m) {
            int2 v = g_csr[base + lane];
            sj = v.x;
            es += __int_as_float(v.y);
        }
#pragma unroll 8
        for (int j = 0; j < m; j++) {
            int s = __shfl_sync(0xffffffffu, sj, j);
            float2 v = __half22float2(yh[(size_t)s * 64 + lane]);
            ax += v.x; ay += v.y;
        }
    }
#pragma unroll
    for (int o = 16; o; o >>= 1) es += __shfl_xor_sync(0xffffffffu, es, o);
    float inv = 1.f / fmaxf((float)(re - rs), 1.f);
    float2 z  = __half22float2(*(const __half2*)&g_h16[(size_t)gw * 128 + 64 + lane * 2]);
    float2 bb = *(const float2*)&bl[lane * 2];
    float rx = fmaxf(ax * inv + bb.x + z.x, 0.f);
    float ry = fmaxf(ay * inv + bb.y + z.y, 0.f);
    *(__half2*)&g_hA16[(size_t)gw * 64 + lane * 2] = __floats2half2_rn(rx, ry);
    if (lane == 0) g_meane[gw] = es * inv;
}

// ---------------- GAT edge pass, lane-parallel alpha, warp per node ---------------
template <int H, bool POOL>
__global__ void k_gat(const float* __restrict__ ssrc,
                      const float* __restrict__ sdst, const float* __restrict__ bias,
                      __half* __restrict__ hout16, int ceoff,
                      const int* __restrict__ types, const int* __restrict__ batch) {
    int n = (blockIdx.x * blockDim.x + threadIdx.x) >> 5;
    int lane = threadIdx.x & 31;
    if (n >= NN) return;
    int rs = g_rowstart[n], re = g_rowstart[n + 1];
    const __half* hp16 = g_h16;

    if constexpr (H == 2) {
        int myhead = lane >> 4;
        float ce0 = g_cE[ceoff], ce1 = g_cE[ceoff + 1];
        float2 sdp = *(const float2*)&sdst[(size_t)n * 2];
        float den;
        float4 acc;
        {   // self-loop
            float2 ssp = *(const float2*)&ssrc[(size_t)n * 2];
            float me = g_meane[n];
            float a0 = ssp.x + sdp.x + me * ce0; a0 = a0 > 0.f ? a0 : 0.2f * a0;
            float a1 = ssp.y + sdp.y + me * ce1; a1 = a1 > 0.f ? a1 : 0.2f * a1;
            float w = __expf(myhead ? a1 : a0);
            uint2 raw = *(const uint2*)(hp16 + (size_t)n * 128 + lane * 4);
            float2 f0 = __half22float2(*(__half2*)&raw.x);
            float2 f1 = __half22float2(*(__half2*)&raw.y);
            den = w;
            acc.x = w * f0.x; acc.y = w * f0.y; acc.z = w * f1.x; acc.w = w * f1.y;
        }
        for (int base = rs; base < re; base += 32) {
            int m = re - base; if (m > 32) m = 32;
            int sj = 0; float w0j = 0.f, w1j = 0.f;
            if (lane < m) {
                int2 v = g_csr[base + lane];
                sj = v.x;
                float ea = __int_as_float(v.y);
                float2 ssp = *(const float2*)&ssrc[(size_t)sj * 2];
                float a0 = ssp.x + sdp.x + ea * ce0; a0 = a0 > 0.f ? a0 : 0.2f * a0;
                float a1 = ssp.y + sdp.y + ea * ce1; a1 = a1 > 0.f ? a1 : 0.2f * a1;
                w0j = __expf(a0); w1j = __expf(a1);
            }
#pragma unroll 8
            for (int j = 0; j < m; j++) {
                int s = __shfl_sync(0xffffffffu, sj, j);
                float w0 = __shfl_sync(0xffffffffu, w0j, j);
                float w1 = __shfl_sync(0xffffffffu, w1j, j);
                float w = myhead ? w1 : w0;
                uint2 raw = *(const uint2*)(hp16 + (size_t)s * 128 + lane * 4);
                float2 f0 = __half22float2(*(__half2*)&raw.x);
                float2 f1 = __half22float2(*(__half2*)&raw.y);
                den += w;
                acc.x = fmaf(w, f0.x, acc.x); acc.y = fmaf(w, f0.y, acc.y);
                acc.z = fmaf(w, f1.x, acc.z); acc.w = fmaf(w, f1.y, acc.w);
            }
        }
        float invd = 1.f / den;
        float4 v = make_float4(acc.x * invd, acc.y * invd, acc.z * invd, acc.w * invd);
        float4 o;
        o.x = __shfl_xor_sync(0xffffffffu, v.x, 16);
        o.y = __shfl_xor_sync(0xffffffffu, v.y, 16);
        o.z = __shfl_xor_sync(0xffffffffu, v.z, 16);
        o.w = __shfl_xor_sync(0xffffffffu, v.w, 16);
        if (lane < 16) {
            float4 bb = *(const float4*)&bias[lane * 4];
            __half2 p0 = __floats2half2_rn(fmaxf((v.x + o.x) * 0.5f + bb.x, 0.f),
                                           fmaxf((v.y + o.y) * 0.5f + bb.y, 0.f));
            __half2 p1 = __floats2half2_rn(fmaxf((v.z + o.z) * 0.5f + bb.z, 0.f),
                                           fmaxf((v.w + o.w) * 0.5f + bb.w, 0.f));
            uint2 u; u.x = *(unsigned*)&p0; u.y = *(unsigned*)&p1;
            *(uint2*)&hout16[(size_t)n * 64 + lane * 4] = u;
        }
    } else {
        float cem = g_cE[ceoff];
        float sdm = sdst[n];
        float den;
        float2 acc;
        {
            float a = ssrc[n] + sdm + g_meane[n] * cem;
            a = a > 0.f ? a : 0.2f * a;
            float w = __expf(a);
            float2 f = __half22float2(*(const __half2*)(hp16 + (size_t)n * 64 + lane * 2));
            den = w; acc.x = w * f.x; acc.y = w * f.y;
        }
        for (int base = rs; base < re; base += 32) {
            int m = re - base; if (m > 32) m = 32;
            int sj = 0; float wj = 0.f;
            if (lane < m) {
                int2 v = g_csr[base + lane];
                sj = v.x;
                float ea = __int_as_float(v.y);
                float a = ssrc[sj] + sdm + ea * cem;
                a = a > 0.f ? a : 0.2f * a;
                wj = __expf(a);
            }
#pragma unroll 8
            for (int j = 0; j < m; j++) {
                int s = __shfl_sync(0xffffffffu, sj, j);
                float w = __shfl_sync(0xffffffffu, wj, j);
                float2 f = __half22float2(*(const __half2*)(hp16 + (size_t)s * 64 + lane * 2));
                den += w;
                acc.x = fmaf(w, f.x, acc.x); acc.y = fmaf(w, f.y, acc.y);
            }
        }
        float invd = 1.f / den;
        float2 bb = *(const float2*)&bias[lane * 2];
        float rx = fmaxf(acc.x * invd + bb.x, 0.f);
        float ry = fmaxf(acc.y * invd + bb.y, 0.f);
        if constexpr (POOL) {
            int t = types[n];
            if (t == 1 || t == 2) {
                int g = batch[n];
                float* base = &g_pool[((t - 1) * GG + g) * 64 + lane * 2];
                atomicAdd(base, rx);
                atomicAdd(base + 1, ry);
                if (lane == 0) atomicAdd(&g_cnt[(t - 1) * GG + g], 1.f);
            }
        } else {
            *(__half2*)&hout16[(size_t)n * 64 + lane * 2] = __floats2half2_rn(rx, ry);
        }
    }
}

// ---------------- final MLP (single block) ----------------
__global__ void k_mlp(const float* __restrict__ w1, const float* __restrict__ b1,
                      const float* __restrict__ w2, const float* __restrict__ b2,
                      float* __restrict__ out) {
    __shared__ float sr[16 * 128];
    __shared__ float sh[16 * 64];
    int tid = threadIdx.x;  // 1024
    for (int idx = tid; idx < 2048; idx += 1024) {
        int g = idx >> 7, c = idx & 127;
        int p = c >> 6, cc = c & 63;
        float cnt = fmaxf(g_cnt[p * GG + g], 1.f);
        sr[idx] = g_pool[(p * GG + g) * 64 + cc] / cnt;
    }
    __syncthreads();
    {
        int g = tid >> 6, o = tid & 63;
        float acc = b1[o];
#pragma unroll 8
        for (int c = 0; c < 128; c++) acc = fmaf(sr[g * 128 + c], w1[o * 128 + c], acc);
        sh[g * 64 + o] = fmaxf(acc, 0.f);
    }
    __syncthreads();
    if (tid < 16) {
        float acc = b2[0];
#pragma unroll 8
        for (int o = 0; o < 64; o++) acc = fmaf(sh[tid * 64 + o], w2[o], acc);
        out[tid] = acc;
    }
}

// ---------------- host ----------------
extern "C" void kernel_launch(void* const* d_in, const int* in_sizes, int n_in,
                              void* d_out, int out_size) {
    const float* x       = (const float*)d_in[0];
    const int*   ei      = (const int*)  d_in[1];
    const int*   types   = (const int*)  d_in[2];
    const float* eattr   = (const float*)d_in[3];
    const int*   batch   = (const int*)  d_in[4];
    const float* sage_wl = (const float*)d_in[5];
    const float* sage_bl = (const float*)d_in[6];
    const float* sage_wr = (const float*)d_in[7];
    const float* mlp_w1  = (const float*)d_in[8];
    const float* mlp_b1  = (const float*)d_in[9];
    const float* mlp_w2  = (const float*)d_in[10];
    const float* mlp_b2  = (const float*)d_in[11];
    const float* g1_w  = (const float*)d_in[12];
    const float* g1_as = (const float*)d_in[13];
    const float* g1_ad = (const float*)d_in[14];
    const float* g1_we = (const float*)d_in[15];
    const float* g1_ae = (const float*)d_in[16];
    const float* g1_b  = (const float*)d_in[17];
    const float* g2_w  = (const float*)d_in[18];
    const float* g2_as = (const float*)d_in[19];
    const float* g2_ad = (const float*)d_in[20];
    const float* g2_we = (const float*)d_in[21];
    const float* g2_ae = (const float*)d_in[22];
    const float* g2_b  = (const float*)d_in[23];
    const float* go_w  = (const float*)d_in[24];
    const float* go_as = (const float*)d_in[25];
    const float* go_ad = (const float*)d_in[26];
    const float* go_we = (const float*)d_in[27];
    const float* go_ae = (const float*)d_in[28];
    const float* go_b  = (const float*)d_in[29];

    const int* src = ei;
    const int* dst = ei + EE;

    float *p_ssrc, *p_sdst;
    int* p_count;
    __half *p_h16, *p_hA16, *p_hB16;
    __half2 *p_wshi, *p_w1, *p_w2, *p_wo;
    cudaGetSymbolAddress((void**)&p_wshi, g_wshi);
    cudaGetSymbolAddress((void**)&p_w1, g_w16_g1);
    cudaGetSymbolAddress((void**)&p_w2, g_w16_g2);
    cudaGetSymbolAddress((void**)&p_wo, g_w16_go);
    cudaGetSymbolAddress((void**)&p_h16, g_h16);
    cudaGetSymbolAddress((void**)&p_hA16, g_hA16);
    cudaGetSymbolAddress((void**)&p_hB16, g_hB16);
    cudaGetSymbolAddress((void**)&p_ssrc, g_ssrc);
    cudaGetSymbolAddress((void**)&p_sdst, g_sdst);
    cudaGetSymbolAddress((void**)&p_count, g_count);

    const int NWARP_GRID = (NN * 32 + 255) / 256;
    const int EGRID = (EE + 255) / 256;
    const int HG_GRID = (NN + 127) / 128;
    const int TF_GRID = (NN + 127) / 128;
    const int TF_SMEM = STAGE_W * 2 * 4;   // 54272 B (2 stages)

    cudaFuncSetAttribute(k_gemm_f16x2, cudaFuncAttributeMaxDynamicSharedMemorySize, TF_SMEM);

    static cudaStream_t s_side = nullptr;
    static cudaEvent_t s_ev0 = nullptr, s_ev2 = nullptr;
    if (!s_side) {
        cudaStreamCreateWithFlags(&s_side, cudaStreamNonBlocking);
        cudaEventCreateWithFlags(&s_ev0, cudaEventDisableTiming);
        cudaEventCreateWithFlags(&s_ev2, cudaEventDisableTiming);
    }

    // Fork FIRST (capture-legal): side stream joins capture via this event,
    // then runs the CSR chain concurrently with prep+GEMM on the main stream.
    cudaEventRecord(s_ev0, 0);
    cudaStreamWaitEvent(s_side, s_ev0, 0);
    cudaMemsetAsync(p_count, 0, NN * sizeof(int), s_side);
    k_hist<<<(EE / 4 + 255) / 256, 256, 0, s_side>>>(dst);
    k_part<<<SNB, 256, 0, s_side>>>();

    // Main: prep + GEMM
    k_prep<<<(NN + 255) / 256, 256>>>(sage_wl, sage_wr, g1_w, g2_w, go_w,
                                      g1_we, g1_ae, g2_we, g2_ae, go_we, go_ae);
    k_gemm_f16x2<<<TF_GRID, 256, TF_SMEM>>>(x, p_wshi, p_h16);

    // Side: finish CSR, then join
    k_scan2<<<1, 64, 0, s_side>>>();
    k_scanfinal<<<SNB, 256, 0, s_side>>>();
    k_scatter<<<EGRID, 256, 0, s_side>>>(src, dst, eattr);
    cudaEventRecord(s_ev2, s_side);
    cudaStreamWaitEvent(0, s_ev2, 0);

    k_sage<<<NWARP_GRID, 256>>>(sage_bl);

    k_hgemm<128, 2><<<HG_GRID, 256>>>(p_hA16, p_w1, p_h16, g1_as, g1_ad, p_ssrc, p_sdst);
    k_gat<2, false><<<NWARP_GRID, 256>>>(p_ssrc, p_sdst, g1_b, p_hB16, 0, nullptr, nullptr);

    k_hgemm<128, 2><<<HG_GRID, 256>>>(p_hB16, p_w2, p_h16, g2_as, g2_ad, p_ssrc, p_sdst);
    k_gat<2, false><<<NWARP_GRID, 256>>>(p_ssrc, p_sdst, g2_b, p_hA16, 2, nullptr, nullptr);

    k_hgemm<64, 1><<<HG_GRID, 256>>>(p_hA16, p_wo, p_h16, go_as, go_ad, p_ssrc, p_sdst);
    k_gat<1, true><<<NWARP_GRID, 256>>>(p_ssrc, p_sdst, go_b, nullptr, 4, types, batch);

    k_mlp<<<1, 1024>>>(mlp_w1, mlp_b1, mlp_w2, mlp_b2, (float*)d_out);
}

// round 16
// speedup vs baseline: 1.0570x; 1.0098x over previous
#include <cuda_runtime.h>
#include <cuda_fp16.h>
#include <math.h>

#define NN   50000
#define EE   800000
#define GG   16
#define SCH  1024
#define SNB  ((NN + SCH - 1) / SCH)   // 49

// ---------------- scratch (device globals; no allocation allowed) ----------------
__device__ int      g_count[NN];
__device__ int      g_rank[EE];          // per-edge rank within its dst bucket
__device__ int      g_rowstart[NN + 1];
__device__ int      g_bsum[SNB];
__device__ int      g_boff[SNB];
__device__ int2     g_csr[EE];           // packed {src, ea-bits}
__device__ __half2  g_wshi[128 * 128];   // SAGE W fp16, [k2][o]
__device__ __half2  g_w16_g1[32 * 128];
__device__ __half2  g_w16_g2[32 * 128];
__device__ __half2  g_w16_go[32 * 64];
__device__ __half   g_h16[(size_t)NN * 128];  // SAGE: [y|z] fp16; GAT: projected feats
__device__ __half   g_hA16[(size_t)NN * 64];
__device__ __half   g_hB16[(size_t)NN * 64];
__device__ float    g_ssrc[(size_t)NN * 2];
__device__ float    g_sdst[(size_t)NN * 2];
__device__ float    g_meane[NN];
__device__ float    g_cE[5];
__device__ float    g_pool[2 * GG * 64];
__device__ float    g_cnt[2 * GG];

__device__ __forceinline__ void cp16(unsigned saddr, const void* g, unsigned sz) {
    asm volatile("cp.async.cg.shared.global [%0], [%1], 16, %2;"
                 :: "r"(saddr), "l"(g), "r"(sz));
}
__device__ __forceinline__ void cp_commit() { asm volatile("cp.async.commit_group;"); }
template <int N>
__device__ __forceinline__ void cp_wait() {
    asm volatile("cp.async.wait_group %0;" :: "n"(N));
}

// ---------------- prep (g_count zeroed by memset node on side stream) -------------
__global__ void k_prep(const float* __restrict__ wl, const float* __restrict__ wr,
                       const float* __restrict__ w1, const float* __restrict__ w2,
                       const float* __restrict__ wo,
                       const float* __restrict__ we1, const float* __restrict__ ae1,
                       const float* __restrict__ we2, const float* __restrict__ ae2,
                       const float* __restrict__ weo, const float* __restrict__ aeo) {
    int i = blockIdx.x * blockDim.x + threadIdx.x;
    if (i < 2 * GG * 64) g_pool[i] = 0.f;
    if (i < 2 * GG) g_cnt[i] = 0.f;
    if (i < 128 * 128) {
        int k2 = i >> 7, o = i & 127;
        int k0 = 2 * k2, k1 = 2 * k2 + 1;
        float w0 = (o < 64) ? wl[o * 256 + k0] : wr[(o - 64) * 256 + k0];
        float w1v = (o < 64) ? wl[o * 256 + k1] : wr[(o - 64) * 256 + k1];
        g_wshi[i] = __floats2half2_rn(w0, w1v);
    }
    if (i < 32 * 128) {
        int k2 = i >> 7, o = i & 127;
        g_w16_g1[i] = __floats2half2_rn(w1[o * 64 + 2 * k2], w1[o * 64 + 2 * k2 + 1]);
        g_w16_g2[i] = __floats2half2_rn(w2[o * 64 + 2 * k2], w2[o * 64 + 2 * k2 + 1]);
    }
    if (i < 32 * 64) {
        int k2 = i >> 6, o = i & 63;
        g_w16_go[i] = __floats2half2_rn(wo[o * 64 + 2 * k2], wo[o * 64 + 2 * k2 + 1]);
    }
    if (blockIdx.x == 0 && threadIdx.x < 160) {
        int wid = threadIdx.x >> 5, lane = threadIdx.x & 31;
        const float *we, *ae;
        if      (wid == 0) { we = we1;      ae = ae1;      }
        else if (wid == 1) { we = we1 + 64; ae = ae1 + 64; }
        else if (wid == 2) { we = we2;      ae = ae2;      }
        else if (wid == 3) { we = we2 + 64; ae = ae2 + 64; }
        else               { we = weo;      ae = aeo;      }
        float p = we[lane] * ae[lane] + we[lane + 32] * ae[lane + 32];
#pragma unroll
        for (int o = 16; o; o >>= 1) p += __shfl_xor_sync(0xffffffffu, p, o);
        if (lane == 0) g_cE[wid] = p;
    }
}

// ---------------- CSR build ----------------
// hist also records each edge's rank within its dst bucket (free from the atomic)
__global__ void k_hist(const int* __restrict__ dst) {
    int e4 = blockIdx.x * blockDim.x + threadIdx.x;
    if (e4 < EE / 4) {
        int e = e4 * 4;
        int4 d = *(const int4*)&dst[e];
        int4 r;
        r.x = atomicAdd(&g_count[d.x], 1);
        r.y = atomicAdd(&g_count[d.y], 1);
        r.z = atomicAdd(&g_count[d.z], 1);
        r.w = atomicAdd(&g_count[d.w], 1);
        *(int4*)&g_rank[e] = r;
    }
}

__global__ void k_part() {
    __shared__ int ws[8];
    int b = blockIdx.x, tid = threadIdx.x;
    int base = b * SCH + tid * 4;
    int s = 0;
#pragma unroll
    for (int j = 0; j < 4; j++) { int i = base + j; if (i < NN) s += g_count[i]; }
#pragma unroll
    for (int o = 16; o; o >>= 1) s += __shfl_down_sync(0xffffffffu, s, o);
    if ((tid & 31) == 0) ws[tid >> 5] = s;
    __syncthreads();
    if (tid == 0) {
        int t = 0;
#pragma unroll
        for (int w = 0; w < 8; w++) t += ws[w];
        g_bsum[b] = t;
    }
}

__global__ void k_scan2() {
    __shared__ int w0s;
    int tid = threadIdx.x, lane = tid & 31, wid = tid >> 5;
    int v = (tid < SNB) ? g_bsum[tid] : 0;
    int s = v;
#pragma unroll
    for (int o = 1; o < 32; o <<= 1) {
        int t = __shfl_up_sync(0xffffffffu, s, o);
        if (lane >= o) s += t;
    }
    if (wid == 0 && lane == 31) w0s = s;
    __syncthreads();
    if (wid == 1) s += w0s;
    if (tid < SNB) g_boff[tid] = s - v;
}

__global__ void k_scanfinal() {
    __shared__ int wsum[8];
    int b = blockIdx.x, tid = threadIdx.x, lane = tid & 31, wid = tid >> 5;
    int base = b * SCH + tid * 4;
    int c[4];
#pragma unroll
    for (int j = 0; j < 4; j++) c[j] = (base + j < NN) ? g_count[base + j] : 0;
    int tsum = c[0] + c[1] + c[2] + c[3];
    int s = tsum;
#pragma unroll
    for (int o = 1; o < 32; o <<= 1) {
        int t = __shfl_up_sync(0xffffffffu, s, o);
        if (lane >= o) s += t;
    }
    int wexcl = s - tsum;
    if (lane == 31) wsum[wid] = s;
    __syncthreads();
    if (tid == 0) {
        int run = 0;
#pragma unroll
        for (int w = 0; w < 8; w++) { int t = wsum[w]; wsum[w] = run; run += t; }
    }
    __syncthreads();
    int off = g_boff[b] + wsum[wid] + wexcl;
#pragma unroll
    for (int j = 0; j < 4; j++) {
        int i = base + j;
        if (i < NN) g_rowstart[i] = off;
        off += c[j];
    }
    if (b == 0 && tid == 0) g_rowstart[NN] = EE;
}

// atomic-free scatter: position = rowstart[dst] + rank (precomputed in hist)
__global__ void k_scatter(const int* __restrict__ src, const int* __restrict__ dst,
                          const float* __restrict__ ea) {
    int e = blockIdx.x * blockDim.x + threadIdx.x;
    if (e < EE) {
        int p = g_rowstart[dst[e]] + g_rank[e];
        g_csr[p] = make_int2(src[e], __float_as_int(ea[e]));
    }
}

// ---------------- SAGE GEMM: fp16 2-term (ah*bh + al*bh), BM=128, BK=32, 2-stage ---
#define ASTR 36
#define BSTR2 136
#define A_WORDS (128 * ASTR)             // 4608 f32 words
#define B_WORDS (16 * BSTR2)             // 2176 half2 words
#define STAGE_W (A_WORDS + B_WORDS)      // 6784 words = 27136 B

__device__ __forceinline__ void mma_f16(float* c, const unsigned* a, unsigned b0, unsigned b1) {
    asm volatile(
        "mma.sync.aligned.m16n8k16.row.col.f32.f16.f16.f32 "
        "{%0,%1,%2,%3}, {%4,%5,%6,%7}, {%8,%9}, {%0,%1,%2,%3};"
        : "+f"(c[0]), "+f"(c[1]), "+f"(c[2]), "+f"(c[3])
        : "r"(a[0]), "r"(a[1]), "r"(a[2]), "r"(a[3]), "r"(b0), "r"(b1));
}

__device__ __forceinline__ void split2(float2 p, unsigned& hi, unsigned& lo) {
    __half h0 = __float2half_rn(p.x), h1 = __float2half_rn(p.y);
    __half l0 = __float2half_rn(p.x - __half2float(h0));
    __half l1 = __float2half_rn(p.y - __half2float(h1));
    __half2 H = __halves2half2(h0, h1), L = __halves2half2(l0, l1);
    hi = *(unsigned*)&H; lo = *(unsigned*)&L;
}

__global__ __launch_bounds__(256) void k_gemm_f16x2(const float* __restrict__ x,
                                                    const __half2* __restrict__ whi,
                                                    __half* __restrict__ h16) {
    extern __shared__ unsigned sm[];
    const int tid = threadIdx.x;
    const int lane = tid & 31, wid = tid >> 5;
    const int wm = wid & 3, wn = wid >> 2;
    const int brow = blockIdx.x * 128;
    const int gid = lane >> 2, tig = lane & 3;

    unsigned smbase = (unsigned)__cvta_generic_to_shared((void*)sm);

    auto load_stage = [&](int kt, int st) {
        const int k0 = kt * 32;
        const int k2b = kt * 16;
        unsigned abase = smbase + (unsigned)(st * STAGE_W) * 4u;
        unsigned bbase = abase + (unsigned)A_WORDS * 4u;
#pragma unroll
        for (int i = 0; i < 4; i++) {
            int r = (tid >> 3) + i * 32;
            int gr = brow + r;
            unsigned sz = (gr < NN) ? 16u : 0u;
            cp16(abase + (unsigned)(r * ASTR + (tid & 7) * 4) * 4u,
                 &x[(size_t)gr * 256 + k0 + (tid & 7) * 4], sz);
        }
        {
            int kr = tid >> 5, c4 = (tid & 31) * 4;
            cp16(bbase + (unsigned)(kr * BSTR2 + c4) * 4u,
                 &whi[(size_t)(k2b + kr) * 128 + c4], 16u);
            cp16(bbase + (unsigned)((kr + 8) * BSTR2 + c4) * 4u,
                 &whi[(size_t)(k2b + kr + 8) * 128 + c4], 16u);
        }
        cp_commit();
    };

    float acc[2][8][4];
#pragma unroll
    for (int m = 0; m < 2; m++)
#pragma unroll
        for (int j = 0; j < 8; j++)
#pragma unroll
            for (int q = 0; q < 4; q++) acc[m][j][q] = 0.f;

    load_stage(0, 0);

    for (int kt = 0; kt < 8; kt++) {
        if (kt < 7) { load_stage(kt + 1, (kt + 1) & 1); cp_wait<1>(); }
        else cp_wait<0>();
        __syncthreads();

        const int st = kt & 1;
        const float* Araw = (const float*)(sm + st * STAGE_W);
        const unsigned* Bhi = sm + st * STAGE_W + A_WORDS;

#pragma unroll
        for (int ko2 = 0; ko2 < 16; ko2 += 8) {
            unsigned ah[2][4], al[2][4];
#pragma unroll
            for (int mt = 0; mt < 2; mt++) {
                int r = wm * 32 + mt * 16 + gid;
                const float* A0 = Araw + r * ASTR + ko2 * 2 + tig * 2;
                const float* A1 = Araw + (r + 8) * ASTR + ko2 * 2 + tig * 2;
                split2(*(const float2*)A0,       ah[mt][0], al[mt][0]);
                split2(*(const float2*)A1,       ah[mt][1], al[mt][1]);
                split2(*(const float2*)(A0 + 8), ah[mt][2], al[mt][2]);
                split2(*(const float2*)(A1 + 8), ah[mt][3], al[mt][3]);
            }
#pragma unroll
            for (int j = 0; j < 8; j++) {
                int col = wn * 64 + j * 8 + gid;
                unsigned b0h = Bhi[(ko2 + tig) * BSTR2 + col];
                unsigned b1h = Bhi[(ko2 + 4 + tig) * BSTR2 + col];
#pragma unroll
                for (int mt = 0; mt < 2; mt++) {
                    mma_f16(acc[mt][j], ah[mt], b0h, b1h);
                    mma_f16(acc[mt][j], al[mt], b0h, b1h);
                }
            }
        }
        __syncthreads();
    }

#pragma unroll
    for (int mt = 0; mt < 2; mt++) {
#pragma unroll
        for (int j = 0; j < 8; j++) {
            int col = wn * 64 + j * 8 + tig * 2;
            int r0 = brow + wm * 32 + mt * 16 + gid;
            int r1 = r0 + 8;
            __half2 h0 = __floats2half2_rn(acc[mt][j][0], acc[mt][j][1]);
            __half2 h1 = __floats2half2_rn(acc[mt][j][2], acc[mt][j][3]);
            if (r0 < NN) *(__half2*)&h16[(size_t)r0 * 128 + col] = h0;
            if (r1 < NN) *(__half2*)&h16[(size_t)r1 * 128 + col] = h1;
        }
    }
}

// ---------------- GAT-layer GEMM via fp16 HMMA (K=64 single tile) ----------------
template <int BN, int H>
__global__ __launch_bounds__(256) void k_hgemm(const __half* __restrict__ in,
                                               const __half2* __restrict__ Wt2,
                                               __half* __restrict__ out16,
                                               const float* __restrict__ as_,
                                               const float* __restrict__ ad_,
                                               float* __restrict__ ssrc,
                                               float* __restrict__ sdst) {
    constexpr int WN = BN / 2;
    constexpr int NJ = WN / 8;
    __shared__ __half  As[128][72];
    __shared__ __half2 Bs[32][BN + 4];
    __shared__ float   sred[2][2][128];

    const int tid = threadIdx.x;
    const int lane = tid & 31, wid = tid >> 5;
    const int wm = wid & 3, wn = wid >> 2;
    const int brow = blockIdx.x * 128;
    const int gid = lane >> 2, tig = lane & 3;

#pragma unroll
    for (int i = 0; i < 4; i++) {
        int q = tid + i * 256;
        int r = q >> 3, c8 = (q & 7) * 8;
        int gr = brow + r;
        uint4 v = make_uint4(0, 0, 0, 0);
        if (gr < NN) v = *(const uint4*)&in[(size_t)gr * 64 + c8];
        *(uint4*)&As[r][c8] = v;
    }
#pragma unroll
    for (int i = 0; i < (BN * 32) / 1024; i++) {
        int q = tid + i * 256;
        int kr = q / (BN / 4), c4 = (q % (BN / 4)) * 4;
        *(uint4*)&Bs[kr][c4] = *(const uint4*)&Wt2[kr * BN + c4];
    }
    __syncthreads();

    float acc[2][NJ][4];
#pragma unroll
    for (int mt = 0; mt < 2; mt++)
#pragma unroll
        for (int j = 0; j < NJ; j++)
#pragma unroll
            for (int q = 0; q < 4; q++) acc[mt][j][q] = 0.f;

#pragma unroll
    for (int ko = 0; ko < 4; ko++) {
        unsigned a[2][4];
#pragma unroll
        for (int mt = 0; mt < 2; mt++) {
            int r = wm * 32 + mt * 16 + gid;
            a[mt][0] = *(unsigned*)&As[r][ko * 16 + tig * 2];
            a[mt][1] = *(unsigned*)&As[r + 8][ko * 16 + tig * 2];
            a[mt][2] = *(unsigned*)&As[r][ko * 16 + 8 + tig * 2];
            a[mt][3] = *(unsigned*)&As[r + 8][ko * 16 + 8 + tig * 2];
        }
#pragma unroll
        for (int j = 0; j < NJ; j++) {
            int col = wn * WN + j * 8 + gid;
            unsigned b0 = *(unsigned*)&Bs[ko * 8 + tig][col];
            unsigned b1 = *(unsigned*)&Bs[ko * 8 + 4 + tig][col];
            mma_f16(acc[0][j], a[0], b0, b1);
            mma_f16(acc[1][j], a[1], b0, b1);
        }
    }

#pragma unroll
    for (int mt = 0; mt < 2; mt++) {
        int r0 = brow + wm * 32 + mt * 16 + gid;
        int r1 = r0 + 8;
        float ps0 = 0.f, pd0 = 0.f, ps1 = 0.f, pd1 = 0.f;
#pragma unroll
        for (int j = 0; j < NJ; j++) {
            int c = wn * WN + j * 8 + tig * 2;
            __half2 h0 = __floats2half2_rn(acc[mt][j][0], acc[mt][j][1]);
            __half2 h1 = __floats2half2_rn(acc[mt][j][2], acc[mt][j][3]);
            if (r0 < NN) *(__half2*)&out16[(size_t)r0 * BN + c] = h0;
            if (r1 < NN) *(__half2*)&out16[(size_t)r1 * BN + c] = h1;
            float a0 = as_[c], a1 = as_[c + 1];
            float d0 = ad_[c], d1 = ad_[c + 1];
            ps0 += acc[mt][j][0] * a0 + acc[mt][j][1] * a1;
            pd0 += acc[mt][j][0] * d0 + acc[mt][j][1] * d1;
            ps1 += acc[mt][j][2] * a0 + acc[mt][j][3] * a1;
            pd1 += acc[mt][j][2] * d0 + acc[mt][j][3] * d1;
        }
#pragma unroll
        for (int o = 2; o; o >>= 1) {
            ps0 += __shfl_down_sync(0xffffffffu, ps0, o, 4);
            pd0 += __shfl_down_sync(0xffffffffu, pd0, o, 4);
            ps1 += __shfl_down_sync(0xffffffffu, ps1, o, 4);
            pd1 += __shfl_down_sync(0xffffffffu, pd1, o, 4);
        }
        if (tig == 0) {
            if constexpr (H == 2) {
                if (r0 < NN) { ssrc[(size_t)r0 * 2 + wn] = ps0; sdst[(size_t)r0 * 2 + wn] = pd0; }
                if (r1 < NN) { ssrc[(size_t)r1 * 2 + wn] = ps1; sdst[(size_t)r1 * 2 + wn] = pd1; }
            } else {
                int rb = wm * 32 + mt * 16 + gid;
                sred[0][wn][rb] = ps0; sred[1][wn][rb] = pd0;
                sred[0][wn][rb + 8] = ps1; sred[1][wn][rb + 8] = pd1;
            }
        }
    }
    if constexpr (H == 1) {
        __syncthreads();
        if (tid < 128) {
            int gr = brow + tid;
            if (gr < NN) {
                ssrc[gr] = sred[0][0][tid] + sred[0][1][tid];
                sdst[gr] = sred[1][0][tid] + sred[1][1][tid];
            }
        }
    }
}

// ---------------- SAGE aggregate: warp per node ----------------
__global__ void k_sage(const float* __restrict__ bl) {
    int gw = (blockIdx.x * blockDim.x + threadIdx.x) >> 5;
    int lane = threadIdx.x & 31;
    if (gw >= NN) return;
    int rs = g_rowstart[gw], re = g_rowstart[gw + 1];
    const __half2* yh = (const __half2*)g_h16;
    float ax = 0.f, ay = 0.f, es = 0.f;
    for (int base = rs; base < re; base += 32) {
        int m = re - base; if (m > 32) m = 32;
        int sj = 0;
        if (lane < m) {
            int2 v = g_csr[base + lane];
            sj = v.x;
            es += __int_as_float(v.y);
        }
#pragma unroll 8
        for (int j = 0; j < m; j++) {
            int s = __shfl_sync(0xffffffffu, sj, j);
            float2 v = __half22float2(yh[(size_t)s * 64 + lane]);
            ax += v.x; ay += v.y;
        }
    }
#pragma unroll
    for (int o = 16; o; o >>= 1) es += __shfl_xor_sync(0xffffffffu, es, o);
    float inv = 1.f / fmaxf((float)(re - rs), 1.f);
    float2 z  = __half22float2(*(const __half2*)&g_h16[(size_t)gw * 128 + 64 + lane * 2]);
    float2 bb = *(const float2*)&bl[lane * 2];
    float rx = fmaxf(ax * inv + bb.x + z.x, 0.f);
    float ry = fmaxf(ay * inv + bb.y + z.y, 0.f);
    *(__half2*)&g_hA16[(size_t)gw * 64 + lane * 2] = __floats2half2_rn(rx, ry);
    if (lane == 0) g_meane[gw] = es * inv;
}

// ---------------- GAT edge pass, lane-parallel alpha, warp per node ---------------
template <int H, bool POOL>
__global__ void k_gat(const float* __restrict__ ssrc,
                      const float* __restrict__ sdst, const float* __restrict__ bias,
                      __half* __restrict__ hout16, int ceoff,
                      const int* __restrict__ types, const int* __restrict__ batch) {
    int n = (blockIdx.x * blockDim.x + threadIdx.x) >> 5;
    int lane = threadIdx.x & 31;
    if (n >= NN) return;
    int rs = g_rowstart[n], re = g_rowstart[n + 1];
    const __half* hp16 = g_h16;

    if constexpr (H == 2) {
        int myhead = lane >> 4;
        float ce0 = g_cE[ceoff], ce1 = g_cE[ceoff + 1];
        float2 sdp = *(const float2*)&sdst[(size_t)n * 2];
        float den;
        float4 acc;
        {   // self-loop
            float2 ssp = *(const float2*)&ssrc[(size_t)n * 2];
            float me = g_meane[n];
            float a0 = ssp.x + sdp.x + me * ce0; a0 = a0 > 0.f ? a0 : 0.2f * a0;
            float a1 = ssp.y + sdp.y + me * ce1; a1 = a1 > 0.f ? a1 : 0.2f * a1;
            float w = __expf(myhead ? a1 : a0);
            uint2 raw = *(const uint2*)(hp16 + (size_t)n * 128 + lane * 4);
            float2 f0 = __half22float2(*(__half2*)&raw.x);
            float2 f1 = __half22float2(*(__half2*)&raw.y);
            den = w;
            acc.x = w * f0.x; acc.y = w * f0.y; acc.z = w * f1.x; acc.w = w * f1.y;
        }
        for (int base = rs; base < re; base += 32) {
            int m = re - base; if (m > 32) m = 32;
            int sj = 0; float w0j = 0.f, w1j = 0.f;
            if (lane < m) {
                int2 v = g_csr[base + lane];
                sj = v.x;
                float ea = __int_as_float(v.y);
                float2 ssp = *(const float2*)&ssrc[(size_t)sj * 2];
                float a0 = ssp.x + sdp.x + ea * ce0; a0 = a0 > 0.f ? a0 : 0.2f * a0;
                float a1 = ssp.y + sdp.y + ea * ce1; a1 = a1 > 0.f ? a1 : 0.2f * a1;
                w0j = __expf(a0); w1j = __expf(a1);
            }
#pragma unroll 8
            for (int j = 0; j < m; j++) {
                int s = __shfl_sync(0xffffffffu, sj, j);
                float w0 = __shfl_sync(0xffffffffu, w0j, j);
                float w1 = __shfl_sync(0xffffffffu, w1j, j);
                float w = myhead ? w1 : w0;
                uint2 raw = *(const uint2*)(hp16 + (size_t)s * 128 + lane * 4);
                float2 f0 = __half22float2(*(__half2*)&raw.x);
                float2 f1 = __half22float2(*(__half2*)&raw.y);
                den += w;
                acc.x = fmaf(w, f0.x, acc.x); acc.y = fmaf(w, f0.y, acc.y);
                acc.z = fmaf(w, f1.x, acc.z); acc.w = fmaf(w, f1.y, acc.w);
            }
        }
        float invd = 1.f / den;
        float4 v = make_float4(acc.x * invd, acc.y * invd, acc.z * invd, acc.w * invd);
        float4 o;
        o.x = __shfl_xor_sync(0xffffffffu, v.x, 16);
        o.y = __shfl_xor_sync(0xffffffffu, v.y, 16);
        o.z = __shfl_xor_sync(0xffffffffu, v.z, 16);
        o.w = __shfl_xor_sync(0xffffffffu, v.w, 16);
        if (lane < 16) {
            float4 bb = *(const float4*)&bias[lane * 4];
            __half2 p0 = __floats2half2_rn(fmaxf((v.x + o.x) * 0.5f + bb.x, 0.f),
                                           fmaxf((v.y + o.y) * 0.5f + bb.y, 0.f));
            __half2 p1 = __floats2half2_rn(fmaxf((v.z + o.z) * 0.5f + bb.z, 0.f),
                                           fmaxf((v.w + o.w) * 0.5f + bb.w, 0.f));
            uint2 u; u.x = *(unsigned*)&p0; u.y = *(unsigned*)&p1;
            *(uint2*)&hout16[(size_t)n * 64 + lane * 4] = u;
        }
    } else {
        float cem = g_cE[ceoff];
        float sdm = sdst[n];
        float den;
        float2 acc;
        {
            float a = ssrc[n] + sdm + g_meane[n] * cem;
            a = a > 0.f ? a : 0.2f * a;
            float w = __expf(a);
            float2 f = __half22float2(*(const __half2*)(hp16 + (size_t)n * 64 + lane * 2));
            den = w; acc.x = w * f.x; acc.y = w * f.y;
        }
        for (int base = rs; base < re; base += 32) {
            int m = re - base; if (m > 32) m = 32;
            int sj = 0; float wj = 0.f;
            if (lane < m) {
                int2 v = g_csr[base + lane];
                sj = v.x;
                float ea = __int_as_float(v.y);
                float a = ssrc[sj] + sdm + ea * cem;
                a = a > 0.f ? a : 0.2f * a;
                wj = __expf(a);
            }
#pragma unroll 8
            for (int j = 0; j < m; j++) {
                int s = __shfl_sync(0xffffffffu, sj, j);
                float w = __shfl_sync(0xffffffffu, wj, j);
                float2 f = __half22float2(*(const __half2*)(hp16 + (size_t)s * 64 + lane * 2));
                den += w;
                acc.x = fmaf(w, f.x, acc.x); acc.y = fmaf(w, f.y, acc.y);
            }
        }
        float invd = 1.f / den;
        float2 bb = *(const float2*)&bias[lane * 2];
        float rx = fmaxf(acc.x * invd + bb.x, 0.f);
        float ry = fmaxf(acc.y * invd + bb.y, 0.f);
        if constexpr (POOL) {
            int t = types[n];
            if (t == 1 || t == 2) {
                int g = batch[n];
                float* base = &g_pool[((t - 1) * GG + g) * 64 + lane * 2];
                atomicAdd(base, rx);
                atomicAdd(base + 1, ry);
                if (lane == 0) atomicAdd(&g_cnt[(t - 1) * GG + g], 1.f);
            }
        } else {
            *(__half2*)&hout16[(size_t)n * 64 + lane * 2] = __floats2half2_rn(rx, ry);
        }
    }
}

// ---------------- final MLP (single block) ----------------
__global__ void k_mlp(const float* __restrict__ w1, const float* __restrict__ b1,
                      const float* __restrict__ w2, const float* __restrict__ b2,
                      float* __restrict__ out) {
    __shared__ float sr[16 * 128];
    __shared__ float sh[16 * 64];
    int tid = threadIdx.x;  // 1024
    for (int idx = tid; idx < 2048; idx += 1024) {
        int g = idx >> 7, c = idx & 127;
        int p = c >> 6, cc = c & 63;
        float cnt = fmaxf(g_cnt[p * GG + g], 1.f);
        sr[idx] = g_pool[(p * GG + g) * 64 + cc] / cnt;
    }
    __syncthreads();
    {
        int g = tid >> 6, o = tid & 63;
        float acc = b1[o];
#pragma unroll 8
        for (int c = 0; c < 128; c++) acc = fmaf(sr[g * 128 + c], w1[o * 128 + c], acc);
        sh[g * 64 + o] = fmaxf(acc, 0.f);
    }
    __syncthreads();
    if (tid < 16) {
        float acc = b2[0];
#pragma unroll 8
        for (int o = 0; o < 64; o++) acc = fmaf(sh[tid * 64 + o], w2[o], acc);
        out[tid] = acc;
    }
}

// ---------------- host ----------------
extern "C" void kernel_launch(void* const* d_in, const int* in_sizes, int n_in,
                              void* d_out, int out_size) {
    const float* x       = (const float*)d_in[0];
    const int*   ei      = (const int*)  d_in[1];
    const int*   types   = (const int*)  d_in[2];
    const float* eattr   = (const float*)d_in[3];
    const int*   batch   = (const int*)  d_in[4];
    const float* sage_wl = (const float*)d_in[5];
    const float* sage_bl = (const float*)d_in[6];
    const float* sage_wr = (const float*)d_in[7];
    const float* mlp_w1  = (const float*)d_in[8];
    const float* mlp_b1  = (const float*)d_in[9];
    const float* mlp_w2  = (const float*)d_in[10];
    const float* mlp_b2  = (const float*)d_in[11];
    const float* g1_w  = (const float*)d_in[12];
    const float* g1_as = (const float*)d_in[13];
    const float* g1_ad = (const float*)d_in[14];
    const float* g1_we = (const float*)d_in[15];
    const float* g1_ae = (const float*)d_in[16];
    const float* g1_b  = (const float*)d_in[17];
    const float* g2_w  = (const float*)d_in[18];
    const float* g2_as = (const float*)d_in[19];
    const float* g2_ad = (const float*)d_in[20];
    const float* g2_we = (const float*)d_in[21];
    const float* g2_ae = (const float*)d_in[22];
    const float* g2_b  = (const float*)d_in[23];
    const float* go_w  = (const float*)d_in[24];
    const float* go_as = (const float*)d_in[25];
    const float* go_ad = (const float*)d_in[26];
    const float* go_we = (const float*)d_in[27];
    const float* go_ae = (const float*)d_in[28];
    const float* go_b  = (const float*)d_in[29];

    const int* src = ei;
    const int* dst = ei + EE;

    float *p_ssrc, *p_sdst;
    int* p_count;
    __half *p_h16, *p_hA16, *p_hB16;
    __half2 *p_wshi, *p_w1, *p_w2, *p_wo;
    cudaGetSymbolAddress((void**)&p_wshi, g_wshi);
    cudaGetSymbolAddress((void**)&p_w1, g_w16_g1);
    cudaGetSymbolAddress((void**)&p_w2, g_w16_g2);
    cudaGetSymbolAddress((void**)&p_wo, g_w16_go);
    cudaGetSymbolAddress((void**)&p_h16, g_h16);
    cudaGetSymbolAddress((void**)&p_hA16, g_hA16);
    cudaGetSymbolAddress((void**)&p_hB16, g_hB16);
    cudaGetSymbolAddress((void**)&p_ssrc, g_ssrc);
    cudaGetSymbolAddress((void**)&p_sdst, g_sdst);
    cudaGetSymbolAddress((void**)&p_count, g_count);

    const int NWARP_GRID = (NN * 32 + 255) / 256;
    const int EGRID = (EE + 255) / 256;
    const int HG_GRID = (NN + 127) / 128;
    const int TF_GRID = (NN + 127) / 128;
    const int TF_SMEM = STAGE_W * 2 * 4;   // 54272 B (2 stages)

    cudaFuncSetAttribute(k_gemm_f16x2, cudaFuncAttributeMaxDynamicSharedMemorySize, TF_SMEM);

    static cudaStream_t s_side = nullptr;
    static cudaEvent_t s_ev0 = nullptr, s_ev2 = nullptr;
    if (!s_side) {
        cudaStreamCreateWithFlags(&s_side, cudaStreamNonBlocking);
        cudaEventCreateWithFlags(&s_ev0, cudaEventDisableTiming);
        cudaEventCreateWithFlags(&s_ev2, cudaEventDisableTiming);
    }

    // Fork FIRST (capture-legal): side stream joins capture via this event,
    // then runs the CSR chain concurrently with prep+GEMM on the main stream.
    cudaEventRecord(s_ev0, 0);
    cudaStreamWaitEvent(s_side, s_ev0, 0);
    cudaMemsetAsync(p_count, 0, NN * sizeof(int), s_side);
    k_hist<<<(EE / 4 + 255) / 256, 256, 0, s_side>>>(dst);
    k_part<<<SNB, 256, 0, s_side>>>();

    // Main: prep + GEMM
    k_prep<<<(NN + 255) / 256, 256>>>(sage_wl, sage_wr, g1_w, g2_w, go_w,
                                      g1_we, g1_ae, g2_we, g2_ae, go_we, go_ae);
    k_gemm_f16x2<<<TF_GRID, 256, TF_SMEM>>>(x, p_wshi, p_h16);

    // Side: finish CSR (scan + atomic-free scatter), then join
    k_scan2<<<1, 64, 0, s_side>>>();
    k_scanfinal<<<SNB, 256, 0, s_side>>>();
    k_scatter<<<EGRID, 256, 0, s_side>>>(src, dst, eattr);
    cudaEventRecord(s_ev2, s_side);
    cudaStreamWaitEvent(0, s_ev2, 0);

    k_sage<<<NWARP_GRID, 256>>>(sage_bl);

    k_hgemm<128, 2><<<HG_GRID, 256>>>(p_hA16, p_w1, p_h16, g1_as, g1_ad, p_ssrc, p_sdst);
    k_gat<2, false><<<NWARP_GRID, 256>>>(p_ssrc, p_sdst, g1_b, p_hB16, 0, nullptr, nullptr);

    k_hgemm<128, 2><<<HG_GRID, 256>>>(p_hB16, p_w2, p_h16, g2_as, g2_ad, p_ssrc, p_sdst);
    k_gat<2, false><<<NWARP_GRID, 256>>>(p_ssrc, p_sdst, g2_b, p_hA16, 2, nullptr, nullptr);

    k_hgemm<64, 1><<<HG_GRID, 256>>>(p_hA16, p_wo, p_h16, go_as, go_ad, p_ssrc, p_sdst);
    k_gat<1, true><<<NWARP_GRID, 256>>>(p_ssrc, p_sdst, go_b, nullptr, 4, types, batch);

    k_mlp<<<1, 1024>>>(mlp_w1, mlp_b1, mlp_w2, mlp_b2, (float*)d_out);
}

// round 17
// speedup vs baseline: 1.0812x; 1.0228x over previous
#include <cuda_runtime.h>
#include <cuda_fp16.h>
#include <math.h>

#define NN   50000
#define EE   800000
#define GG   16
#define SCH  1024
#define SNB  ((NN + SCH - 1) / SCH)   // 49

// ---------------- scratch (device globals; no allocation allowed) ----------------
__device__ int      g_count[NN];
__device__ int      g_rank[EE];          // per-edge rank within its dst bucket
__device__ int      g_rowstart[NN + 1];
__device__ int      g_bsum[SNB];
__device__ int      g_boff[SNB];
__device__ int2     g_csr[EE];           // packed {src, ea-bits}
__device__ __half2  g_wshi[128 * 128];   // SAGE W fp16, [k2][o]
__device__ __half2  g_w16_g1[32 * 128];
__device__ __half2  g_w16_g2[32 * 128];
__device__ __half2  g_w16_go[32 * 64];
__device__ __half   g_h16[(size_t)NN * 128];  // SAGE: [y|z] fp16; GAT: projected feats
__device__ __half   g_hA16[(size_t)NN * 64];
__device__ __half   g_hB16[(size_t)NN * 64];
__device__ float    g_ssrc[(size_t)NN * 2];
__device__ float    g_sdst[(size_t)NN * 2];
__device__ float    g_meane[NN];
__device__ float    g_cE[5];
__device__ float    g_pool[2 * GG * 64];
__device__ float    g_cnt[2 * GG];

__device__ __forceinline__ void cp16(unsigned saddr, const void* g, unsigned sz) {
    asm volatile("cp.async.cg.shared.global [%0], [%1], 16, %2;"
                 :: "r"(saddr), "l"(g), "r"(sz));
}
__device__ __forceinline__ void cp_commit() { asm volatile("cp.async.commit_group;"); }
template <int N>
__device__ __forceinline__ void cp_wait() {
    asm volatile("cp.async.wait_group %0;" :: "n"(N));
}
// PDL: wait for all stream-order dependencies' memory to be visible.
__device__ __forceinline__ void pdl_sync() {
    asm volatile("griddepcontrol.wait;" ::: "memory");
}

// ---------------- prep (g_count zeroed by memset node on side stream) -------------
__global__ void k_prep(const float* __restrict__ wl, const float* __restrict__ wr,
                       const float* __restrict__ w1, const float* __restrict__ w2,
                       const float* __restrict__ wo,
                       const float* __restrict__ we1, const float* __restrict__ ae1,
                       const float* __restrict__ we2, const float* __restrict__ ae2,
                       const float* __restrict__ weo, const float* __restrict__ aeo) {
    int i = blockIdx.x * blockDim.x + threadIdx.x;
    if (i < 2 * GG * 64) g_pool[i] = 0.f;
    if (i < 2 * GG) g_cnt[i] = 0.f;
    if (i < 128 * 128) {
        int k2 = i >> 7, o = i & 127;
        int k0 = 2 * k2, k1 = 2 * k2 + 1;
        float w0 = (o < 64) ? wl[o * 256 + k0] : wr[(o - 64) * 256 + k0];
        float w1v = (o < 64) ? wl[o * 256 + k1] : wr[(o - 64) * 256 + k1];
        g_wshi[i] = __floats2half2_rn(w0, w1v);
    }
    if (i < 32 * 128) {
        int k2 = i >> 7, o = i & 127;
        g_w16_g1[i] = __floats2half2_rn(w1[o * 64 + 2 * k2], w1[o * 64 + 2 * k2 + 1]);
        g_w16_g2[i] = __floats2half2_rn(w2[o * 64 + 2 * k2], w2[o * 64 + 2 * k2 + 1]);
    }
    if (i < 32 * 64) {
        int k2 = i >> 6, o = i & 63;
        g_w16_go[i] = __floats2half2_rn(wo[o * 64 + 2 * k2], wo[o * 64 + 2 * k2 + 1]);
    }
    if (blockIdx.x == 0 && threadIdx.x < 160) {
        int wid = threadIdx.x >> 5, lane = threadIdx.x & 31;
        const float *we, *ae;
        if      (wid == 0) { we = we1;      ae = ae1;      }
        else if (wid == 1) { we = we1 + 64; ae = ae1 + 64; }
        else if (wid == 2) { we = we2;      ae = ae2;      }
        else if (wid == 3) { we = we2 + 64; ae = ae2 + 64; }
        else               { we = weo;      ae = aeo;      }
        float p = we[lane] * ae[lane] + we[lane + 32] * ae[lane + 32];
#pragma unroll
        for (int o = 16; o; o >>= 1) p += __shfl_xor_sync(0xffffffffu, p, o);
        if (lane == 0) g_cE[wid] = p;
    }
}

// ---------------- CSR build ----------------
__global__ void k_hist(const int* __restrict__ dst) {
    int e4 = blockIdx.x * blockDim.x + threadIdx.x;
    if (e4 < EE / 4) {
        int e = e4 * 4;
        int4 d = *(const int4*)&dst[e];
        int4 r;
        r.x = atomicAdd(&g_count[d.x], 1);
        r.y = atomicAdd(&g_count[d.y], 1);
        r.z = atomicAdd(&g_count[d.z], 1);
        r.w = atomicAdd(&g_count[d.w], 1);
        *(int4*)&g_rank[e] = r;
    }
}

__global__ void k_part() {
    __shared__ int ws[8];
    int b = blockIdx.x, tid = threadIdx.x;
    int base = b * SCH + tid * 4;
    int s = 0;
#pragma unroll
    for (int j = 0; j < 4; j++) { int i = base + j; if (i < NN) s += g_count[i]; }
#pragma unroll
    for (int o = 16; o; o >>= 1) s += __shfl_down_sync(0xffffffffu, s, o);
    if ((tid & 31) == 0) ws[tid >> 5] = s;
    __syncthreads();
    if (tid == 0) {
        int t = 0;
#pragma unroll
        for (int w = 0; w < 8; w++) t += ws[w];
        g_bsum[b] = t;
    }
}

__global__ void k_scan2() {
    __shared__ int w0s;
    int tid = threadIdx.x, lane = tid & 31, wid = tid >> 5;
    int v = (tid < SNB) ? g_bsum[tid] : 0;
    int s = v;
#pragma unroll
    for (int o = 1; o < 32; o <<= 1) {
        int t = __shfl_up_sync(0xffffffffu, s, o);
        if (lane >= o) s += t;
    }
    if (wid == 0 && lane == 31) w0s = s;
    __syncthreads();
    if (wid == 1) s += w0s;
    if (tid < SNB) g_boff[tid] = s - v;
}

__global__ void k_scanfinal() {
    __shared__ int wsum[8];
    int b = blockIdx.x, tid = threadIdx.x, lane = tid & 31, wid = tid >> 5;
    int base = b * SCH + tid * 4;
    int c[4];
#pragma unroll
    for (int j = 0; j < 4; j++) c[j] = (base + j < NN) ? g_count[base + j] : 0;
    int tsum = c[0] + c[1] + c[2] + c[3];
    int s = tsum;
#pragma unroll
    for (int o = 1; o < 32; o <<= 1) {
        int t = __shfl_up_sync(0xffffffffu, s, o);
        if (lane >= o) s += t;
    }
    int wexcl = s - tsum;
    if (lane == 31) wsum[wid] = s;
    __syncthreads();
    if (tid == 0) {
        int run = 0;
#pragma unroll
        for (int w = 0; w < 8; w++) { int t = wsum[w]; wsum[w] = run; run += t; }
    }
    __syncthreads();
    int off = g_boff[b] + wsum[wid] + wexcl;
#pragma unroll
    for (int j = 0; j < 4; j++) {
        int i = base + j;
        if (i < NN) g_rowstart[i] = off;
        off += c[j];
    }
    if (b == 0 && tid == 0) g_rowstart[NN] = EE;
}

// atomic-free scatter: position = rowstart[dst] + rank (precomputed in hist)
__global__ void k_scatter(const int* __restrict__ src, const int* __restrict__ dst,
                          const float* __restrict__ ea) {
    int e = blockIdx.x * blockDim.x + threadIdx.x;
    if (e < EE) {
        int p = g_rowstart[dst[e]] + g_rank[e];
        g_csr[p] = make_int2(src[e], __float_as_int(ea[e]));
    }
}

// ---------------- SAGE GEMM: fp16 2-term (ah*bh + al*bh), BM=128, BK=32, 2-stage ---
#define ASTR 36
#define BSTR2 136
#define A_WORDS (128 * ASTR)             // 4608 f32 words
#define B_WORDS (16 * BSTR2)             // 2176 half2 words
#define STAGE_W (A_WORDS + B_WORDS)      // 6784 words = 27136 B

__device__ __forceinline__ void mma_f16(float* c, const unsigned* a, unsigned b0, unsigned b1) {
    asm volatile(
        "mma.sync.aligned.m16n8k16.row.col.f32.f16.f16.f32 "
        "{%0,%1,%2,%3}, {%4,%5,%6,%7}, {%8,%9}, {%0,%1,%2,%3};"
        : "+f"(c[0]), "+f"(c[1]), "+f"(c[2]), "+f"(c[3])
        : "r"(a[0]), "r"(a[1]), "r"(a[2]), "r"(a[3]), "r"(b0), "r"(b1));
}

__device__ __forceinline__ void split2(float2 p, unsigned& hi, unsigned& lo) {
    __half h0 = __float2half_rn(p.x), h1 = __float2half_rn(p.y);
    __half l0 = __float2half_rn(p.x - __half2float(h0));
    __half l1 = __float2half_rn(p.y - __half2float(h1));
    __half2 H = __halves2half2(h0, h1), L = __halves2half2(l0, l1);
    hi = *(unsigned*)&H; lo = *(unsigned*)&L;
}

__global__ __launch_bounds__(256) void k_gemm_f16x2(const float* __restrict__ x,
                                                    const __half2* __restrict__ whi,
                                                    __half* __restrict__ h16) {
    extern __shared__ unsigned sm[];
    const int tid = threadIdx.x;
    const int lane = tid & 31, wid = tid >> 5;
    const int wm = wid & 3, wn = wid >> 2;
    const int brow = blockIdx.x * 128;
    const int gid = lane >> 2, tig = lane & 3;

    unsigned smbase = (unsigned)__cvta_generic_to_shared((void*)sm);

    auto load_stage = [&](int kt, int st) {
        const int k0 = kt * 32;
        const int k2b = kt * 16;
        unsigned abase = smbase + (unsigned)(st * STAGE_W) * 4u;
        unsigned bbase = abase + (unsigned)A_WORDS * 4u;
#pragma unroll
        for (int i = 0; i < 4; i++) {
            int r = (tid >> 3) + i * 32;
            int gr = brow + r;
            unsigned sz = (gr < NN) ? 16u : 0u;
            cp16(abase + (unsigned)(r * ASTR + (tid & 7) * 4) * 4u,
                 &x[(size_t)gr * 256 + k0 + (tid & 7) * 4], sz);
        }
        {
            int kr = tid >> 5, c4 = (tid & 31) * 4;
            cp16(bbase + (unsigned)(kr * BSTR2 + c4) * 4u,
                 &whi[(size_t)(k2b + kr) * 128 + c4], 16u);
            cp16(bbase + (unsigned)((kr + 8) * BSTR2 + c4) * 4u,
                 &whi[(size_t)(k2b + kr + 8) * 128 + c4], 16u);
        }
        cp_commit();
    };

    float acc[2][8][4];
#pragma unroll
    for (int m = 0; m < 2; m++)
#pragma unroll
        for (int j = 0; j < 8; j++)
#pragma unroll
            for (int q = 0; q < 4; q++) acc[m][j][q] = 0.f;

    load_stage(0, 0);

    for (int kt = 0; kt < 8; kt++) {
        if (kt < 7) { load_stage(kt + 1, (kt + 1) & 1); cp_wait<1>(); }
        else cp_wait<0>();
        __syncthreads();

        const int st = kt & 1;
        const float* Araw = (const float*)(sm + st * STAGE_W);
        const unsigned* Bhi = sm + st * STAGE_W + A_WORDS;

#pragma unroll
        for (int ko2 = 0; ko2 < 16; ko2 += 8) {
            unsigned ah[2][4], al[2][4];
#pragma unroll
            for (int mt = 0; mt < 2; mt++) {
                int r = wm * 32 + mt * 16 + gid;
                const float* A0 = Araw + r * ASTR + ko2 * 2 + tig * 2;
                const float* A1 = Araw + (r + 8) * ASTR + ko2 * 2 + tig * 2;
                split2(*(const float2*)A0,       ah[mt][0], al[mt][0]);
                split2(*(const float2*)A1,       ah[mt][1], al[mt][1]);
                split2(*(const float2*)(A0 + 8), ah[mt][2], al[mt][2]);
                split2(*(const float2*)(A1 + 8), ah[mt][3], al[mt][3]);
            }
#pragma unroll
            for (int j = 0; j < 8; j++) {
                int col = wn * 64 + j * 8 + gid;
                unsigned b0h = Bhi[(ko2 + tig) * BSTR2 + col];
                unsigned b1h = Bhi[(ko2 + 4 + tig) * BSTR2 + col];
#pragma unroll
                for (int mt = 0; mt < 2; mt++) {
                    mma_f16(acc[mt][j], ah[mt], b0h, b1h);
                    mma_f16(acc[mt][j], al[mt], b0h, b1h);
                }
            }
        }
        __syncthreads();
    }

#pragma unroll
    for (int mt = 0; mt < 2; mt++) {
#pragma unroll
        for (int j = 0; j < 8; j++) {
            int col = wn * 64 + j * 8 + tig * 2;
            int r0 = brow + wm * 32 + mt * 16 + gid;
            int r1 = r0 + 8;
            __half2 h0 = __floats2half2_rn(acc[mt][j][0], acc[mt][j][1]);
            __half2 h1 = __floats2half2_rn(acc[mt][j][2], acc[mt][j][3]);
            if (r0 < NN) *(__half2*)&h16[(size_t)r0 * 128 + col] = h0;
            if (r1 < NN) *(__half2*)&h16[(size_t)r1 * 128 + col] = h1;
        }
    }
}

// ---------------- GAT-layer GEMM via fp16 HMMA (K=64 single tile), PDL -----------
template <int BN, int H>
__global__ __launch_bounds__(256) void k_hgemm(const __half* __restrict__ in,
                                               const __half2* __restrict__ Wt2,
                                               __half* __restrict__ out16,
                                               const float* __restrict__ as_,
                                               const float* __restrict__ ad_,
                                               float* __restrict__ ssrc,
                                               float* __restrict__ sdst) {
    constexpr int WN = BN / 2;
    constexpr int NJ = WN / 8;
    __shared__ __half  As[128][72];
    __shared__ __half2 Bs[32][BN + 4];
    __shared__ float   sred[2][2][128];

    const int tid = threadIdx.x;
    const int lane = tid & 31, wid = tid >> 5;
    const int wm = wid & 3, wn = wid >> 2;
    const int brow = blockIdx.x * 128;
    const int gid = lane >> 2, tig = lane & 3;

    // safe prologue: weights (written by k_prep, transitively complete)
#pragma unroll
    for (int i = 0; i < (BN * 32) / 1024; i++) {
        int q = tid + i * 256;
        int kr = q / (BN / 4), c4 = (q % (BN / 4)) * 4;
        *(uint4*)&Bs[kr][c4] = *(const uint4*)&Wt2[kr * BN + c4];
    }

    pdl_sync();   // wait for predecessor (activations producer)

#pragma unroll
    for (int i = 0; i < 4; i++) {
        int q = tid + i * 256;
        int r = q >> 3, c8 = (q & 7) * 8;
        int gr = brow + r;
        uint4 v = make_uint4(0, 0, 0, 0);
        if (gr < NN) v = *(const uint4*)&in[(size_t)gr * 64 + c8];
        *(uint4*)&As[r][c8] = v;
    }
    __syncthreads();

    float acc[2][NJ][4];
#pragma unroll
    for (int mt = 0; mt < 2; mt++)
#pragma unroll
        for (int j = 0; j < NJ; j++)
#pragma unroll
            for (int q = 0; q < 4; q++) acc[mt][j][q] = 0.f;

#pragma unroll
    for (int ko = 0; ko < 4; ko++) {
        unsigned a[2][4];
#pragma unroll
        for (int mt = 0; mt < 2; mt++) {
            int r = wm * 32 + mt * 16 + gid;
            a[mt][0] = *(unsigned*)&As[r][ko * 16 + tig * 2];
            a[mt][1] = *(unsigned*)&As[r + 8][ko * 16 + tig * 2];
            a[mt][2] = *(unsigned*)&As[r][ko * 16 + 8 + tig * 2];
            a[mt][3] = *(unsigned*)&As[r + 8][ko * 16 + 8 + tig * 2];
        }
#pragma unroll
        for (int j = 0; j < NJ; j++) {
            int col = wn * WN + j * 8 + gid;
            unsigned b0 = *(unsigned*)&Bs[ko * 8 + tig][col];
            unsigned b1 = *(unsigned*)&Bs[ko * 8 + 4 + tig][col];
            mma_f16(acc[0][j], a[0], b0, b1);
            mma_f16(acc[1][j], a[1], b0, b1);
        }
    }

#pragma unroll
    for (int mt = 0; mt < 2; mt++) {
        int r0 = brow + wm * 32 + mt * 16 + gid;
        int r1 = r0 + 8;
        float ps0 = 0.f, pd0 = 0.f, ps1 = 0.f, pd1 = 0.f;
#pragma unroll
        for (int j = 0; j < NJ; j++) {
            int c = wn * WN + j * 8 + tig * 2;
            __half2 h0 = __floats2half2_rn(acc[mt][j][0], acc[mt][j][1]);
            __half2 h1 = __floats2half2_rn(acc[mt][j][2], acc[mt][j][3]);
            if (r0 < NN) *(__half2*)&out16[(size_t)r0 * BN + c] = h0;
            if (r1 < NN) *(__half2*)&out16[(size_t)r1 * BN + c] = h1;
            float a0 = as_[c], a1 = as_[c + 1];
            float d0 = ad_[c], d1 = ad_[c + 1];
            ps0 += acc[mt][j][0] * a0 + acc[mt][j][1] * a1;
            pd0 += acc[mt][j][0] * d0 + acc[mt][j][1] * d1;
            ps1 += acc[mt][j][2] * a0 + acc[mt][j][3] * a1;
            pd1 += acc[mt][j][2] * d0 + acc[mt][j][3] * d1;
        }
#pragma unroll
        for (int o = 2; o; o >>= 1) {
            ps0 += __shfl_down_sync(0xffffffffu, ps0, o, 4);
            pd0 += __shfl_down_sync(0xffffffffu, pd0, o, 4);
            ps1 += __shfl_down_sync(0xffffffffu, ps1, o, 4);
            pd1 += __shfl_down_sync(0xffffffffu, pd1, o, 4);
        }
        if (tig == 0) {
            if constexpr (H == 2) {
                if (r0 < NN) { ssrc[(size_t)r0 * 2 + wn] = ps0; sdst[(size_t)r0 * 2 + wn] = pd0; }
                if (r1 < NN) { ssrc[(size_t)r1 * 2 + wn] = ps1; sdst[(size_t)r1 * 2 + wn] = pd1; }
            } else {
                int rb = wm * 32 + mt * 16 + gid;
                sred[0][wn][rb] = ps0; sred[1][wn][rb] = pd0;
                sred[0][wn][rb + 8] = ps1; sred[1][wn][rb + 8] = pd1;
            }
        }
    }
    if constexpr (H == 1) {
        __syncthreads();
        if (tid < 128) {
            int gr = brow + tid;
            if (gr < NN) {
                ssrc[gr] = sred[0][0][tid] + sred[0][1][tid];
                sdst[gr] = sred[1][0][tid] + sred[1][1][tid];
            }
        }
    }
}

// ---------------- SAGE aggregate: warp per node, PDL ----------------
__global__ void k_sage(const float* __restrict__ bl) {
    pdl_sync();
    int gw = (blockIdx.x * blockDim.x + threadIdx.x) >> 5;
    int lane = threadIdx.x & 31;
    if (gw >= NN) return;
    int rs = g_rowstart[gw], re = g_rowstart[gw + 1];
    const __half2* yh = (const __half2*)g_h16;
    float ax = 0.f, ay = 0.f, es = 0.f;
    for (int base = rs; base < re; base += 32) {
        int m = re - base; if (m > 32) m = 32;
        int sj = 0;
        if (lane < m) {
            int2 v = g_csr[base + lane];
            sj = v.x;
            es += __int_as_float(v.y);
        }
#pragma unroll 8
        for (int j = 0; j < m; j++) {
            int s = __shfl_sync(0xffffffffu, sj, j);
            float2 v = __half22float2(yh[(size_t)s * 64 + lane]);
            ax += v.x; ay += v.y;
        }
    }
#pragma unroll
    for (int o = 16; o; o >>= 1) es += __shfl_xor_sync(0xffffffffu, es, o);
    float inv = 1.f / fmaxf((float)(re - rs), 1.f);
    float2 z  = __half22float2(*(const __half2*)&g_h16[(size_t)gw * 128 + 64 + lane * 2]);
    float2 bb = *(const float2*)&bl[lane * 2];
    float rx = fmaxf(ax * inv + bb.x + z.x, 0.f);
    float ry = fmaxf(ay * inv + bb.y + z.y, 0.f);
    *(__half2*)&g_hA16[(size_t)gw * 64 + lane * 2] = __floats2half2_rn(rx, ry);
    if (lane == 0) g_meane[gw] = es * inv;
}

// ---------------- GAT edge pass, lane-parallel alpha, warp per node, PDL ----------
template <int H, bool POOL>
__global__ void k_gat(const float* __restrict__ ssrc,
                      const float* __restrict__ sdst, const float* __restrict__ bias,
                      __half* __restrict__ hout16, int ceoff,
                      const int* __restrict__ types, const int* __restrict__ batch) {
    pdl_sync();
    int n = (blockIdx.x * blockDim.x + threadIdx.x) >> 5;
    int lane = threadIdx.x & 31;
    if (n >= NN) return;
    int rs = g_rowstart[n], re = g_rowstart[n + 1];
    const __half* hp16 = g_h16;

    if constexpr (H == 2) {
        int myhead = lane >> 4;
        float ce0 = g_cE[ceoff], ce1 = g_cE[ceoff + 1];
        float2 sdp = *(const float2*)&sdst[(size_t)n * 2];
        float den;
        float4 acc;
        {   // self-loop
            float2 ssp = *(const float2*)&ssrc[(size_t)n * 2];
            float me = g_meane[n];
            float a0 = ssp.x + sdp.x + me * ce0; a0 = a0 > 0.f ? a0 : 0.2f * a0;
            float a1 = ssp.y + sdp.y + me * ce1; a1 = a1 > 0.f ? a1 : 0.2f * a1;
            float w = __expf(myhead ? a1 : a0);
            uint2 raw = *(const uint2*)(hp16 + (size_t)n * 128 + lane * 4);
            float2 f0 = __half22float2(*(__half2*)&raw.x);
            float2 f1 = __half22float2(*(__half2*)&raw.y);
            den = w;
            acc.x = w * f0.x; acc.y = w * f0.y; acc.z = w * f1.x; acc.w = w * f1.y;
        }
        for (int base = rs; base < re; base += 32) {
            int m = re - base; if (m > 32) m = 32;
            int sj = 0; float w0j = 0.f, w1j = 0.f;
            if (lane < m) {
                int2 v = g_csr[base + lane];
                sj = v.x;
                float ea = __int_as_float(v.y);
                float2 ssp = *(const float2*)&ssrc[(size_t)sj * 2];
                float a0 = ssp.x + sdp.x + ea * ce0; a0 = a0 > 0.f ? a0 : 0.2f * a0;
                float a1 = ssp.y + sdp.y + ea * ce1; a1 = a1 > 0.f ? a1 : 0.2f * a1;
                w0j = __expf(a0); w1j = __expf(a1);
            }
#pragma unroll 8
            for (int j = 0; j < m; j++) {
                int s = __shfl_sync(0xffffffffu, sj, j);
                float w0 = __shfl_sync(0xffffffffu, w0j, j);
                float w1 = __shfl_sync(0xffffffffu, w1j, j);
                float w = myhead ? w1 : w0;
                uint2 raw = *(const uint2*)(hp16 + (size_t)s * 128 + lane * 4);
                float2 f0 = __half22float2(*(__half2*)&raw.x);
                float2 f1 = __half22float2(*(__half2*)&raw.y);
                den += w;
                acc.x = fmaf(w, f0.x, acc.x); acc.y = fmaf(w, f0.y, acc.y);
                acc.z = fmaf(w, f1.x, acc.z); acc.w = fmaf(w, f1.y, acc.w);
            }
        }
        float invd = 1.f / den;
        float4 v = make_float4(acc.x * invd, acc.y * invd, acc.z * invd, acc.w * invd);
        float4 o;
        o.x = __shfl_xor_sync(0xffffffffu, v.x, 16);
        o.y = __shfl_xor_sync(0xffffffffu, v.y, 16);
        o.z = __shfl_xor_sync(0xffffffffu, v.z, 16);
        o.w = __shfl_xor_sync(0xffffffffu, v.w, 16);
        if (lane < 16) {
            float4 bb = *(const float4*)&bias[lane * 4];
            __half2 p0 = __floats2half2_rn(fmaxf((v.x + o.x) * 0.5f + bb.x, 0.f),
                                           fmaxf((v.y + o.y) * 0.5f + bb.y, 0.f));
            __half2 p1 = __floats2half2_rn(fmaxf((v.z + o.z) * 0.5f + bb.z, 0.f),
                                           fmaxf((v.w + o.w) * 0.5f + bb.w, 0.f));
            uint2 u; u.x = *(unsigned*)&p0; u.y = *(unsigned*)&p1;
            *(uint2*)&hout16[(size_t)n * 64 + lane * 4] = u;
        }
    } else {
        float cem = g_cE[ceoff];
        float sdm = sdst[n];
        float den;
        float2 acc;
        {
            float a = ssrc[n] + sdm + g_meane[n] * cem;
            a = a > 0.f ? a : 0.2f * a;
            float w = __expf(a);
            float2 f = __half22float2(*(const __half2*)(hp16 + (size_t)n * 64 + lane * 2));
            den = w; acc.x = w * f.x; acc.y = w * f.y;
        }
        for (int base = rs; base < re; base += 32) {
            int m = re - base; if (m > 32) m = 32;
            int sj = 0; float wj = 0.f;
            if (lane < m) {
                int2 v = g_csr[base + lane];
                sj = v.x;
                float ea = __int_as_float(v.y);
                float a = ssrc[sj] + sdm + ea * cem;
                a = a > 0.f ? a : 0.2f * a;
                wj = __expf(a);
            }
#pragma unroll 8
            for (int j = 0; j < m; j++) {
                int s = __shfl_sync(0xffffffffu, sj, j);
                float w = __shfl_sync(0xffffffffu, wj, j);
                float2 f = __half22float2(*(const __half2*)(hp16 + (size_t)s * 64 + lane * 2));
                den += w;
                acc.x = fmaf(w, f.x, acc.x); acc.y = fmaf(w, f.y, acc.y);
            }
        }
        float invd = 1.f / den;
        float2 bb = *(const float2*)&bias[lane * 2];
        float rx = fmaxf(acc.x * invd + bb.x, 0.f);
        float ry = fmaxf(acc.y * invd + bb.y, 0.f);
        if constexpr (POOL) {
            int t = types[n];
            if (t == 1 || t == 2) {
                int g = batch[n];
                float* base = &g_pool[((t - 1) * GG + g) * 64 + lane * 2];
                atomicAdd(base, rx);
                atomicAdd(base + 1, ry);
                if (lane == 0) atomicAdd(&g_cnt[(t - 1) * GG + g], 1.f);
            }
        } else {
            *(__half2*)&hout16[(size_t)n * 64 + lane * 2] = __floats2half2_rn(rx, ry);
        }
    }
}

// ---------------- final MLP (single block), PDL ----------------
__global__ void k_mlp(const float* __restrict__ w1, const float* __restrict__ b1,
                      const float* __restrict__ w2, const float* __restrict__ b2,
                      float* __restrict__ out) {
    __shared__ float sr[16 * 128];
    __shared__ float sh[16 * 64];
    pdl_sync();
    int tid = threadIdx.x;  // 1024
    for (int idx = tid; idx < 2048; idx += 1024) {
        int g = idx >> 7, c = idx & 127;
        int p = c >> 6, cc = c & 63;
        float cnt = fmaxf(g_cnt[p * GG + g], 1.f);
        sr[idx] = g_pool[(p * GG + g) * 64 + cc] / cnt;
    }
    __syncthreads();
    {
        int g = tid >> 6, o = tid & 63;
        float acc = b1[o];
#pragma unroll 8
        for (int c = 0; c < 128; c++) acc = fmaf(sr[g * 128 + c], w1[o * 128 + c], acc);
        sh[g * 64 + o] = fmaxf(acc, 0.f);
    }
    __syncthreads();
    if (tid < 16) {
        float acc = b2[0];
#pragma unroll 8
        for (int o = 0; o < 64; o++) acc = fmaf(sh[tid * 64 + o], w2[o], acc);
        out[tid] = acc;
    }
}

// ---------------- host ----------------
extern "C" void kernel_launch(void* const* d_in, const int* in_sizes, int n_in,
                              void* d_out, int out_size) {
    const float* x       = (const float*)d_in[0];
    const int*   ei      = (const int*)  d_in[1];
    const int*   types   = (const int*)  d_in[2];
    const float* eattr   = (const float*)d_in[3];
    const int*   batch   = (const int*)  d_in[4];
    const float* sage_wl = (const float*)d_in[5];
    const float* sage_bl = (const float*)d_in[6];
    const float* sage_wr = (const float*)d_in[7];
    const float* mlp_w1  = (const float*)d_in[8];
    const float* mlp_b1  = (const float*)d_in[9];
    const float* mlp_w2  = (const float*)d_in[10];
    const float* mlp_b2  = (const float*)d_in[11];
    const float* g1_w  = (const float*)d_in[12];
    const float* g1_as = (const float*)d_in[13];
    const float* g1_ad = (const float*)d_in[14];
    const float* g1_we = (const float*)d_in[15];
    const float* g1_ae = (const float*)d_in[16];
    const float* g1_b  = (const float*)d_in[17];
    const float* g2_w  = (const float*)d_in[18];
    const float* g2_as = (const float*)d_in[19];
    const float* g2_ad = (const float*)d_in[20];
    const float* g2_we = (const float*)d_in[21];
    const float* g2_ae = (const float*)d_in[22];
    const float* g2_b  = (const float*)d_in[23];
    const float* go_w  = (const float*)d_in[24];
    const float* go_as = (const float*)d_in[25];
    const float* go_ad = (const float*)d_in[26];
    const float* go_we = (const float*)d_in[27];
    const float* go_ae = (const float*)d_in[28];
    const float* go_b  = (const float*)d_in[29];

    const int* src = ei;
    const int* dst = ei + EE;

    float *p_ssrc, *p_sdst;
    int* p_count;
    __half *p_h16, *p_hA16, *p_hB16;
    __half2 *p_wshi, *p_w1, *p_w2, *p_wo;
    cudaGetSymbolAddress((void**)&p_wshi, g_wshi);
    cudaGetSymbolAddress((void**)&p_w1, g_w16_g1);
    cudaGetSymbolAddress((void**)&p_w2, g_w16_g2);
    cudaGetSymbolAddress((void**)&p_wo, g_w16_go);
    cudaGetSymbolAddress((void**)&p_h16, g_h16);
    cudaGetSymbolAddress((void**)&p_hA16, g_hA16);
    cudaGetSymbolAddress((void**)&p_hB16, g_hB16);
    cudaGetSymbolAddress((void**)&p_ssrc, g_ssrc);
    cudaGetSymbolAddress((void**)&p_sdst, g_sdst);
    cudaGetSymbolAddress((void**)&p_count, g_count);

    const int NWARP_GRID = (NN * 32 + 255) / 256;
    const int EGRID = (EE + 255) / 256;
    const int HG_GRID = (NN + 127) / 128;
    const int TF_GRID = (NN + 127) / 128;
    const int TF_SMEM = STAGE_W * 2 * 4;   // 54272 B (2 stages)

    cudaFuncSetAttribute(k_gemm_f16x2, cudaFuncAttributeMaxDynamicSharedMemorySize, TF_SMEM);

    static cudaStream_t s_side = nullptr;
    static cudaEvent_t s_ev0 = nullptr, s_ev2 = nullptr;
    if (!s_side) {
        cudaStreamCreateWithFlags(&s_side, cudaStreamNonBlocking);
        cudaEventCreateWithFlags(&s_ev0, cudaEventDisableTiming);
        cudaEventCreateWithFlags(&s_ev2, cudaEventDisableTiming);
    }

    // PDL launch config (stream 0, back-end chain)
    cudaLaunchAttribute pdlAttr;
    pdlAttr.id = cudaLaunchAttributeProgrammaticStreamSerialization;
    pdlAttr.val.programmaticStreamSerializationAllowed = 1;
    cudaLaunchConfig_t cfg = {};
    cfg.stream = 0;
    cfg.attrs = &pdlAttr;
    cfg.numAttrs = 1;

    // Fork FIRST (capture-legal): side stream joins capture via this event,
    // then runs the CSR chain concurrently with prep+GEMM on the main stream.
    cudaEventRecord(s_ev0, 0);
    cudaStreamWaitEvent(s_side, s_ev0, 0);
    cudaMemsetAsync(p_count, 0, NN * sizeof(int), s_side);
    k_hist<<<(EE / 4 + 255) / 256, 256, 0, s_side>>>(dst);
    k_part<<<SNB, 256, 0, s_side>>>();

    // Main: prep + GEMM
    k_prep<<<(NN + 255) / 256, 256>>>(sage_wl, sage_wr, g1_w, g2_w, go_w,
                                      g1_we, g1_ae, g2_we, g2_ae, go_we, go_ae);
    k_gemm_f16x2<<<TF_GRID, 256, TF_SMEM>>>(x, p_wshi, p_h16);

    // Side: finish CSR (scan + atomic-free scatter), then join
    k_scan2<<<1, 64, 0, s_side>>>();
    k_scanfinal<<<SNB, 256, 0, s_side>>>();
    k_scatter<<<EGRID, 256, 0, s_side>>>(src, dst, eattr);
    cudaEventRecord(s_ev2, s_side);
    cudaStreamWaitEvent(0, s_ev2, 0);

    // Back-end chain with PDL boundaries
    cfg.gridDim = dim3(NWARP_GRID); cfg.blockDim = dim3(256); cfg.dynamicSmemBytes = 0;
    cudaLaunchKernelEx(&cfg, k_sage, sage_bl);

    cfg.gridDim = dim3(HG_GRID);
    cudaLaunchKernelEx(&cfg, k_hgemm<128, 2>, (const __half*)p_hA16, (const __half2*)p_w1,
                       (__half*)p_h16, g1_as, g1_ad, (float*)p_ssrc, (float*)p_sdst);
    cfg.gridDim = dim3(NWARP_GRID);
    cudaLaunchKernelEx(&cfg, k_gat<2, false>, (const float*)p_ssrc, (const float*)p_sdst,
                       g1_b, (__half*)p_hB16, 0, (const int*)nullptr, (const int*)nullptr);

    cfg.gridDim = dim3(HG_GRID);
    cudaLaunchKernelEx(&cfg, k_hgemm<128, 2>, (const __half*)p_hB16, (const __half2*)p_w2,
                       (__half*)p_h16, g2_as, g2_ad, (float*)p_ssrc, (float*)p_sdst);
    cfg.gridDim = dim3(NWARP_GRID);
    cudaLaunchKernelEx(&cfg, k_gat<2, false>, (const float*)p_ssrc, (const float*)p_sdst,
                       g2_b, (__half*)p_hA16, 2, (const int*)nullptr, (const int*)nullptr);

    cfg.gridDim = dim3(HG_GRID);
    cudaLaunchKernelEx(&cfg, k_hgemm<64, 1>, (const __half*)p_hA16, (const __half2*)p_wo,
                       (__half*)p_h16, go_as, go_ad, (float*)p_ssrc, (float*)p_sdst);
    cfg.gridDim = dim3(NWARP_GRID);
    cudaLaunchKernelEx(&cfg, k_gat<1, true>, (const float*)p_ssrc, (const float*)p_sdst,
                       go_b, (__half*)nullptr, 4, types, batch);

    cfg.gridDim = dim3(1); cfg.blockDim = dim3(1024);
    cudaLaunchKernelEx(&cfg, k_mlp, mlp_w1, mlp_b1, mlp_w2, mlp_b2, (float*)d_out);
}